// round 12
// baseline (speedup 1.0000x reference)
#include <cuda_runtime.h>
#include <cuda_bf16.h>
#include <math.h>
#include <cstdint>

// Problem constants
#define BB 4
#define SS 4096
#define DD 1024
#define HH 16
#define DH 64
#define MM (BB * SS)          // 16384 rows
#define CC 64                 // chunk length
#define NC (SS / CC)          // 64 chunks per sequence
#define EPS 1e-6f

// ---------------------------------------------------------------------------
// Scratch (device globals; no allocation allowed)
// ---------------------------------------------------------------------------
__device__ __align__(256) float g_q[(size_t)MM * DD];
__device__ __align__(256) float g_k[(size_t)MM * DD];
__device__ __align__(256) float g_v[(size_t)MM * DD];
__device__ __align__(256) __nv_bfloat16 g_xhi[(size_t)MM * DD];
__device__ __align__(256) __nv_bfloat16 g_xlo[(size_t)MM * DD];
__device__ __align__(256) __nv_bfloat16 g_ahi[(size_t)MM * DD];
__device__ __align__(256) __nv_bfloat16 g_alo[(size_t)MM * DD];
// transposed weights [N,K] bf16, hi/lo, 4 weights (q,k,v,o) -- q,k,v contiguous
__device__ __align__(256) __nv_bfloat16 g_wthi[4][(size_t)DD * DD];
__device__ __align__(256) __nv_bfloat16 g_wtlo[4][(size_t)DD * DD];
// chunk states: [B*H][NC][DH][DH]
__device__ __align__(256) float g_cS[(size_t)BB * HH * NC * DH * DH];
__device__ __align__(256) float g_cz[(size_t)BB * HH * NC * DH];

// ---------------------------------------------------------------------------
// Warp-MMA + cp.async helpers (sm_80-era PTX; assembles for sm_103)
// ---------------------------------------------------------------------------
__device__ __forceinline__ uint32_t smem_u32(const void* p) {
    uint32_t a;
    asm("{ .reg .u64 t; cvta.to.shared.u64 t, %1; cvt.u32.u64 %0, t; }"
        : "=r"(a) : "l"(p));
    return a;
}
__device__ __forceinline__ void ldsm_x4(uint32_t* r, uint32_t addr) {
    asm volatile("ldmatrix.sync.aligned.m8n8.x4.shared.b16 {%0,%1,%2,%3}, [%4];"
                 : "=r"(r[0]), "=r"(r[1]), "=r"(r[2]), "=r"(r[3]) : "r"(addr));
}
__device__ __forceinline__ void mma_bf16(float* d, const uint32_t* a,
                                         uint32_t b0, uint32_t b1) {
    asm volatile(
        "mma.sync.aligned.m16n8k16.row.col.f32.bf16.bf16.f32 "
        "{%0,%1,%2,%3}, {%4,%5,%6,%7}, {%8,%9}, {%0,%1,%2,%3};"
        : "+f"(d[0]), "+f"(d[1]), "+f"(d[2]), "+f"(d[3])
        : "r"(a[0]), "r"(a[1]), "r"(a[2]), "r"(a[3]), "r"(b0), "r"(b1));
}
__device__ __forceinline__ void cpa16(uint32_t dst, const void* src) {
    asm volatile("cp.async.cg.shared.global [%0], [%1], 16;"
                 :: "r"(dst), "l"(src));
}
#define CP_COMMIT() asm volatile("cp.async.commit_group;" ::: "memory")
#define CP_WAIT1()  asm volatile("cp.async.wait_group 1;" ::: "memory")

// ---------------------------------------------------------------------------
// Pipelined mma.sync bf16 GEMM with hi/lo split (3 accumulating passes):
// C[:,n] = (Ahi+Alo)[M,K] @ (Bhi+Blo)[Ntot,K]^T, fp32 out.
// CTA 128x128, BK=32, 16 warps (4x4), warp tile 32x32 (lower regs -> 4
// warps/SMSP to feed the tensor pipe). 2-stage cp.async double buffering
// (R10 shape). which=n0>>10 selects output; phimask bit -> elu+1 epilogue.
// ---------------------------------------------------------------------------
#define GBK 32
#define NKCH (DD / GBK)       // 32
#define ASTR 40               // padded smem row stride (bf16) - conflict-free
#define STG (128 * ASTR)      // elems per tile buffer
#define GEMM_SMEM (2 * 4 * STG * 2)   // 2 stages x 4 tiles x 10240 B = 81920

__global__ __launch_bounds__(512, 1) void gemm_mma(const __nv_bfloat16* __restrict__ Ahi,
                                                   const __nv_bfloat16* __restrict__ Alo,
                                                   const __nv_bfloat16* __restrict__ Bhi,
                                                   const __nv_bfloat16* __restrict__ Blo,
                                                   float* __restrict__ c0,
                                                   float* __restrict__ c1,
                                                   float* __restrict__ c2,
                                                   int phimask) {
    extern __shared__ __nv_bfloat16 smbuf[];
    uint32_t bsm = smem_u32(smbuf);

    int tid  = threadIdx.x;
    int wid  = tid >> 5;      // 0..15
    int lane = tid & 31;
    int wr   = wid >> 2;      // 0..3  (M, 32 rows each)
    int wc   = wid & 3;       // 0..3  (N, 32 cols each)
    int m0   = blockIdx.y * 128;
    int n0   = blockIdx.x * 128;

    // per-thread load coords: ONE 16B chunk per tile per stage (512 thr * 16B = tile)
    int rc = tid >> 2;
    int cc = (tid & 3) * 8;
    uint32_t off = (uint32_t)(rc * ASTR + cc) * 2;

    const __nv_bfloat16* gAh = Ahi + (size_t)(m0 + rc) * DD + cc;
    const __nv_bfloat16* gAl = Alo + (size_t)(m0 + rc) * DD + cc;
    const __nv_bfloat16* gBh = Bhi + (size_t)(n0 + rc) * DD + cc;
    const __nv_bfloat16* gBl = Blo + (size_t)(n0 + rc) * DD + cc;

    auto issue = [&](int ch, int s) {
        int k0 = ch * GBK;
        uint32_t base = bsm + (uint32_t)(s * 4) * (uint32_t)(STG * 2);
        cpa16(base + 0 * STG * 2 + off, gAh + k0);
        cpa16(base + 1 * STG * 2 + off, gAl + k0);
        cpa16(base + 2 * STG * 2 + off, gBh + k0);
        cpa16(base + 3 * STG * 2 + off, gBl + k0);
    };

    float acc[2][4][4];
#pragma unroll
    for (int i = 0; i < 2; ++i)
#pragma unroll
        for (int j = 0; j < 4; ++j)
#pragma unroll
            for (int r = 0; r < 4; ++r) acc[i][j][r] = 0.f;

    // ldmatrix base coords
    uint32_t aRow = wr * 32 + (lane & 15);
    uint32_t aCol = (lane >> 4) * 8;
    uint32_t bRow = wc * 32 + (lane & 7);
    uint32_t bCol = (lane >> 3) * 8;

    issue(0, 0); CP_COMMIT();
    issue(1, 1); CP_COMMIT();

    int cur = 0;
    for (int ch = 0; ch < NKCH; ++ch) {
        CP_WAIT1();
        __syncthreads();

        uint32_t base = bsm + (uint32_t)(cur * 4) * (uint32_t)(STG * 2);
        uint32_t bAh = base, bAl = base + STG * 2;
        uint32_t bBh = base + 2 * STG * 2, bBl = base + 3 * STG * 2;

        // B fragments for the whole BK=32 chunk: fb*[nt][k-slice 0..3]
        uint32_t fbh[4][4], fbl[4][4];
#pragma unroll
        for (int nt = 0; nt < 4; ++nt) {
            uint32_t o = ((bRow + nt * 8) * ASTR + bCol) * 2;
            ldsm_x4(fbh[nt], bBh + o);
            ldsm_x4(fbl[nt], bBl + o);
        }
#pragma unroll
        for (int ks = 0; ks < 2; ++ks) {
            uint32_t fah[2][4], fal[2][4];
#pragma unroll
            for (int mt = 0; mt < 2; ++mt) {
                uint32_t o = ((aRow + mt * 16) * ASTR + ks * 16 + aCol) * 2;
                ldsm_x4(fah[mt], bAh + o);
                ldsm_x4(fal[mt], bAl + o);
            }
#pragma unroll
            for (int mt = 0; mt < 2; ++mt)
#pragma unroll
                for (int nt = 0; nt < 4; ++nt) {
                    uint32_t b0 = fbh[nt][ks * 2], b1 = fbh[nt][ks * 2 + 1];
                    uint32_t c0r = fbl[nt][ks * 2], c1r = fbl[nt][ks * 2 + 1];
                    mma_bf16(acc[mt][nt], fah[mt], b0, b1);    // Ah*Bh
                    mma_bf16(acc[mt][nt], fah[mt], c0r, c1r);  // Ah*Bl
                    mma_bf16(acc[mt][nt], fal[mt], b0, b1);    // Al*Bh
                }
        }
        __syncthreads();
        if (ch + 2 < NKCH) issue(ch + 2, cur);
        CP_COMMIT();
        cur ^= 1;
    }

    // epilogue
    int which = n0 >> 10;
    float* C  = (which == 0) ? c0 : ((which == 1) ? c1 : c2);
    int mode  = (phimask >> which) & 1;
    int ncol  = n0 & 1023;
    int erow  = m0 + wr * 32 + (lane >> 2);
    int ecol  = ncol + wc * 32 + (lane & 3) * 2;
#pragma unroll
    for (int mt = 0; mt < 2; ++mt) {
#pragma unroll
        for (int nt = 0; nt < 4; ++nt) {
            float v0 = acc[mt][nt][0], v1 = acc[mt][nt][1];
            float v2 = acc[mt][nt][2], v3 = acc[mt][nt][3];
            if (mode) {
                v0 = (v0 > 0.f) ? (v0 + 1.f) : expf(v0);
                v1 = (v1 > 0.f) ? (v1 + 1.f) : expf(v1);
                v2 = (v2 > 0.f) ? (v2 + 1.f) : expf(v2);
                v3 = (v3 > 0.f) ? (v3 + 1.f) : expf(v3);
            }
            float* p0 = C + (size_t)(erow + mt * 16) * DD + ecol + nt * 8;
            float* p1 = C + (size_t)(erow + mt * 16 + 8) * DD + ecol + nt * 8;
            *(float2*)p0 = make_float2(v0, v1);
            *(float2*)p1 = make_float2(v2, v3);
        }
    }
}

// ---------------------------------------------------------------------------
// x -> bf16 hi/lo split (elementwise)
// ---------------------------------------------------------------------------
__global__ __launch_bounds__(256) void convert_x(const float* __restrict__ x,
                                                 __nv_bfloat16* __restrict__ hi,
                                                 __nv_bfloat16* __restrict__ lo) {
    size_t i4 = ((size_t)blockIdx.x * 256 + threadIdx.x) * 4;
    float4 v = *(const float4*)(x + i4);
    __nv_bfloat16 h0 = __float2bfloat16(v.x), h1 = __float2bfloat16(v.y);
    __nv_bfloat16 h2 = __float2bfloat16(v.z), h3 = __float2bfloat16(v.w);
    __nv_bfloat16 l0 = __float2bfloat16(v.x - __bfloat162float(h0));
    __nv_bfloat16 l1 = __float2bfloat16(v.y - __bfloat162float(h1));
    __nv_bfloat16 l2 = __float2bfloat16(v.z - __bfloat162float(h2));
    __nv_bfloat16 l3 = __float2bfloat16(v.w - __bfloat162float(h3));
    __nv_bfloat162 ph0; ph0.x = h0; ph0.y = h1;
    __nv_bfloat162 ph1; ph1.x = h2; ph1.y = h3;
    __nv_bfloat162 pl0; pl0.x = l0; pl0.y = l1;
    __nv_bfloat162 pl1; pl1.x = l2; pl1.y = l3;
    *(__nv_bfloat162*)(hi + i4)     = ph0;
    *(__nv_bfloat162*)(hi + i4 + 2) = ph1;
    *(__nv_bfloat162*)(lo + i4)     = pl0;
    *(__nv_bfloat162*)(lo + i4 + 2) = pl1;
}

// ---------------------------------------------------------------------------
// All 4 weights: W [K,N] fp32 -> Wt [N,K] bf16 hi/lo (transpose + split)
// grid (32,32,4); z selects weight
// ---------------------------------------------------------------------------
__global__ __launch_bounds__(256) void wconv_all(const float* __restrict__ W0,
                                                 const float* __restrict__ W1,
                                                 const float* __restrict__ W2,
                                                 const float* __restrict__ W3,
                                                 __nv_bfloat16* __restrict__ WhiB,
                                                 __nv_bfloat16* __restrict__ WloB) {
    __shared__ float ts[32][33];
    int z = blockIdx.z;
    const float* W = (z == 0) ? W0 : (z == 1) ? W1 : (z == 2) ? W2 : W3;
    __nv_bfloat16* Whi = WhiB + (size_t)z * DD * DD;
    __nv_bfloat16* Wlo = WloB + (size_t)z * DD * DD;
    int n0 = blockIdx.x * 32, k0 = blockIdx.y * 32;
    int tx = threadIdx.x, ty = threadIdx.y;
#pragma unroll
    for (int j = 0; j < 4; ++j)
        ts[ty + j * 8][tx] = W[(size_t)(k0 + ty + j * 8) * DD + n0 + tx];
    __syncthreads();
#pragma unroll
    for (int j = 0; j < 4; ++j) {
        float v = ts[tx][ty + j * 8];
        __nv_bfloat16 h = __float2bfloat16(v);
        __nv_bfloat16 l = __float2bfloat16(v - __bfloat162float(h));
        size_t o = (size_t)(n0 + ty + j * 8) * DD + k0 + tx;
        Whi[o] = h;
        Wlo[o] = l;
    }
}

// ---------------------------------------------------------------------------
// Per-chunk sums: cS[bid] = K_chunk^T @ V_chunk (64x64), cz[bid] = colsum(K)
// ---------------------------------------------------------------------------
__global__ __launch_bounds__(256) void chunk_sums(const float* __restrict__ k,
                                                  const float* __restrict__ v,
                                                  float* __restrict__ cS,
                                                  float* __restrict__ cz) {
    __shared__ float Ks[64 * 64];
    __shared__ float Vs[64 * 64];

    int bid = blockIdx.x;
    int bh  = bid >> 6;
    int c   = bid & 63;
    int b   = bh >> 4;
    int tid = threadIdx.x;

    size_t gbase = ((size_t)(b * SS + c * CC)) * DD + (size_t)(bh & 15) * DH;
    for (int t4 = tid; t4 < 1024; t4 += 256) {
        int row = t4 >> 4;
        int c4  = (t4 & 15) * 4;
        *(float4*)&Ks[row * 64 + c4] = *(const float4*)&k[gbase + (size_t)row * DD + c4];
        *(float4*)&Vs[row * 64 + c4] = *(const float4*)&v[gbase + (size_t)row * DD + c4];
    }
    __syncthreads();

    int d  = tid >> 2;
    int eb = (tid & 3) * 16;
    float acc[16];
#pragma unroll
    for (int ee = 0; ee < 16; ++ee) acc[ee] = 0.f;

    for (int t = 0; t < 64; ++t) {
        float kd = Ks[t * 64 + d];
        const float4* vr = (const float4*)&Vs[t * 64 + eb];
        float4 v0 = vr[0], v1 = vr[1], v2 = vr[2], v3 = vr[3];
        acc[0]  += kd * v0.x; acc[1]  += kd * v0.y; acc[2]  += kd * v0.z; acc[3]  += kd * v0.w;
        acc[4]  += kd * v1.x; acc[5]  += kd * v1.y; acc[6]  += kd * v1.z; acc[7]  += kd * v1.w;
        acc[8]  += kd * v2.x; acc[9]  += kd * v2.y; acc[10] += kd * v2.z; acc[11] += kd * v2.w;
        acc[12] += kd * v3.x; acc[13] += kd * v3.y; acc[14] += kd * v3.z; acc[15] += kd * v3.w;
    }
    float* out = cS + (size_t)bid * 4096 + d * 64 + eb;
#pragma unroll
    for (int e4 = 0; e4 < 4; ++e4)
        *(float4*)&out[e4 * 4] = make_float4(acc[e4 * 4], acc[e4 * 4 + 1],
                                             acc[e4 * 4 + 2], acc[e4 * 4 + 3]);

    if (tid < 64) {
        float zsum = 0.f;
        for (int t = 0; t < 64; ++t) zsum += Ks[t * 64 + tid];
        cz[(size_t)bid * 64 + tid] = zsum;
    }
}

// ---------------------------------------------------------------------------
// Exclusive prefix over chunks, seeded with state_cache.
// ---------------------------------------------------------------------------
__global__ __launch_bounds__(256) void prefix_kernel(const float* __restrict__ cache,
                                                     float* __restrict__ cS,
                                                     float* __restrict__ cz) {
    int bh  = blockIdx.x;
    int tid = threadIdx.x;

    float run[16];
    {
        int f0 = tid * 16;
#pragma unroll
        for (int u = 0; u < 16; ++u) {
            int f = f0 + u;
            int d = f >> 6, e = f & 63;
            run[u] = cache[((size_t)bh * 65 + d) * 64 + e];
        }
    }
    float runz = (tid < 64) ? cache[((size_t)bh * 65 + 64) * 64 + tid] : 0.f;

    for (int c = 0; c < NC; ++c) {
        size_t base = ((size_t)(bh * NC + c)) * 4096 + (size_t)tid * 16;
#pragma unroll
        for (int u = 0; u < 16; ++u) {
            float t = cS[base + u];
            cS[base + u] = run[u];
            run[u] += t;
        }
        if (tid < 64) {
            size_t zb = ((size_t)(bh * NC + c)) * 64 + tid;
            float t = cz[zb];
            cz[zb] = runz;
            runz += t;
        }
    }
}

// ---------------------------------------------------------------------------
// Intra-chunk causal attention + inter-chunk state application.
// Writes bf16 hi/lo activations for the Wo GEMM.
// ---------------------------------------------------------------------------
#define PSTR 68
#define SMEM_INTRA ((5 * 64 * PSTR + 64) * 4)

__global__ __launch_bounds__(256) void intra_kernel(const float* __restrict__ q,
                                                    const float* __restrict__ k,
                                                    const float* __restrict__ v,
                                                    const float* __restrict__ cS,
                                                    const float* __restrict__ cz,
                                                    __nv_bfloat16* __restrict__ ahi,
                                                    __nv_bfloat16* __restrict__ alo) {
    extern __shared__ float sm[];
    float* Qs = sm;
    float* Ks = sm + 64 * PSTR;
    float* Vs = sm + 2 * 64 * PSTR;
    float* Ss = sm + 3 * 64 * PSTR;
    float* As = sm + 4 * 64 * PSTR;
    float* zs = sm + 5 * 64 * PSTR;

    int bid = blockIdx.x;
    int bh  = bid >> 6;
    int c   = bid & 63;
    int b   = bh >> 4;
    int tid = threadIdx.x;

    size_t gbase = ((size_t)(b * SS + c * CC)) * DD + (size_t)(bh & 15) * DH;
    for (int t4 = tid; t4 < 1024; t4 += 256) {
        int row = t4 >> 4;
        int c4  = (t4 & 15) * 4;
        size_t go = gbase + (size_t)row * DD + c4;
        *(float4*)&Qs[row * PSTR + c4] = *(const float4*)&q[go];
        *(float4*)&Ks[row * PSTR + c4] = *(const float4*)&k[go];
        *(float4*)&Vs[row * PSTR + c4] = *(const float4*)&v[go];
        *(float4*)&Ss[row * PSTR + c4] = *(const float4*)&cS[(size_t)bid * 4096 + (size_t)t4 * 4];
    }
    if (tid < 64) zs[tid] = cz[(size_t)bid * 64 + tid];
    __syncthreads();

    int i  = tid >> 2;
    int q4 = tid & 3;
    int eb = q4 * 16;
    const float* qrow = &Qs[i * PSTR];

    // Phase A: masked A row strip + den (strided j = jj*4+q4)
    float ap[16];
#pragma unroll
    for (int jj = 0; jj < 16; ++jj) ap[jj] = 0.f;
    for (int d = 0; d < 64; ++d) {
        float qd = qrow[d];
#pragma unroll
        for (int jj = 0; jj < 16; ++jj)
            ap[jj] += qd * Ks[(jj * 4 + q4) * PSTR + d];
    }
    float den = 0.f;
#pragma unroll
    for (int jj = 0; jj < 16; ++jj) {
        int j = jj * 4 + q4;
        if (j > i) ap[jj] = 0.f;
        As[i * PSTR + j] = ap[jj];
        den += ap[jj];
    }
#pragma unroll
    for (int dd = 0; dd < 16; ++dd) {
        int d = dd * 4 + q4;
        den += qrow[d] * zs[d];
    }
    den += __shfl_xor_sync(0xffffffffu, den, 1);
    den += __shfl_xor_sync(0xffffffffu, den, 2);
    float inv = 1.f / (den + EPS);
    __syncthreads();

    // Phase B: num = Q @ S_start + A @ V   (contiguous e = eb..eb+15, float4)
    float num[16];
#pragma unroll
    for (int ee = 0; ee < 16; ++ee) num[ee] = 0.f;
    for (int d = 0; d < 64; ++d) {
        float qd = qrow[d];
        const float4* sr = (const float4*)&Ss[d * PSTR + eb];
        float4 s0 = sr[0], s1 = sr[1], s2 = sr[2], s3 = sr[3];
        num[0]  += qd * s0.x; num[1]  += qd * s0.y; num[2]  += qd * s0.z; num[3]  += qd * s0.w;
        num[4]  += qd * s1.x; num[5]  += qd * s1.y; num[6]  += qd * s1.z; num[7]  += qd * s1.w;
        num[8]  += qd * s2.x; num[9]  += qd * s2.y; num[10] += qd * s2.z; num[11] += qd * s2.w;
        num[12] += qd * s3.x; num[13] += qd * s3.y; num[14] += qd * s3.z; num[15] += qd * s3.w;
    }
    for (int j = 0; j < 64; ++j) {
        float aij = As[i * PSTR + j];
        const float4* vr = (const float4*)&Vs[j * PSTR + eb];
        float4 v0 = vr[0], v1 = vr[1], v2 = vr[2], v3 = vr[3];
        num[0]  += aij * v0.x; num[1]  += aij * v0.y; num[2]  += aij * v0.z; num[3]  += aij * v0.w;
        num[4]  += aij * v1.x; num[5]  += aij * v1.y; num[6]  += aij * v1.z; num[7]  += aij * v1.w;
        num[8]  += aij * v2.x; num[9]  += aij * v2.y; num[10] += aij * v2.z; num[11] += aij * v2.w;
        num[12] += aij * v3.x; num[13] += aij * v3.y; num[14] += aij * v3.z; num[15] += aij * v3.w;
    }

    size_t obase = gbase + (size_t)i * DD + eb;
#pragma unroll
    for (int ee = 0; ee < 16; ++ee) {
        float r = num[ee] * inv;
        __nv_bfloat16 h = __float2bfloat16(r);
        __nv_bfloat16 l = __float2bfloat16(r - __bfloat162float(h));
        ahi[obase + ee] = h;
        alo[obase + ee] = l;
    }
}

// ---------------------------------------------------------------------------
// Launch
// ---------------------------------------------------------------------------
extern "C" void kernel_launch(void* const* d_in, const int* in_sizes, int n_in,
                              void* d_out, int out_size) {
    const float* x     = (const float*)d_in[0];
    const float* cache = (const float*)d_in[1];
    const float* Wq    = (const float*)d_in[2];
    const float* Wk    = (const float*)d_in[3];
    const float* Wv    = (const float*)d_in[4];
    const float* Wo    = (const float*)d_in[5];
    float* out = (float*)d_out;

    float *qp, *kp, *vp, *cSp, *czp;
    __nv_bfloat16 *xhi, *xlo, *ahi, *alo, *wthi, *wtlo;
    cudaGetSymbolAddress((void**)&qp,   g_q);
    cudaGetSymbolAddress((void**)&kp,   g_k);
    cudaGetSymbolAddress((void**)&vp,   g_v);
    cudaGetSymbolAddress((void**)&cSp,  g_cS);
    cudaGetSymbolAddress((void**)&czp,  g_cz);
    cudaGetSymbolAddress((void**)&xhi,  g_xhi);
    cudaGetSymbolAddress((void**)&xlo,  g_xlo);
    cudaGetSymbolAddress((void**)&ahi,  g_ahi);
    cudaGetSymbolAddress((void**)&alo,  g_alo);
    cudaGetSymbolAddress((void**)&wthi, g_wthi);
    cudaGetSymbolAddress((void**)&wtlo, g_wtlo);

    cudaFuncSetAttribute(intra_kernel, cudaFuncAttributeMaxDynamicSharedMemorySize,
                         SMEM_INTRA);
    cudaFuncSetAttribute(gemm_mma, cudaFuncAttributeMaxDynamicSharedMemorySize,
                         GEMM_SMEM);

    const size_t WSTRIDE = (size_t)DD * DD;
    const size_t HALF = (size_t)MM * DD / 2;

    // Launch order keeps the fused QKV GEMM at launch #4 for ncu capture.
    wconv_all<<<dim3(32, 32, 4), dim3(32, 8)>>>(Wq, Wk, Wv, Wo, wthi, wtlo);
    convert_x<<<MM * DD / 2048, 256>>>(x, xhi, xlo);
    convert_x<<<MM * DD / 2048, 256>>>(x + HALF, xhi + HALF, xlo + HALF);

    // Fused QKV GEMM: B rows span concatenated [Wq^T | Wk^T | Wv^T] (3072 rows)
    gemm_mma<<<dim3(24, 128), 512, GEMM_SMEM>>>(xhi, xlo, wthi, wtlo,
                                                qp, kp, vp, 0b011);

    chunk_sums<<<BB * HH * NC, 256>>>(kp, vp, cSp, czp);
    prefix_kernel<<<BB * HH, 256>>>(cache, cSp, czp);
    intra_kernel<<<BB * HH * NC, 256, SMEM_INTRA>>>(qp, kp, vp, cSp, czp, ahi, alo);

    // Wo GEMM
    gemm_mma<<<dim3(8, 128), 512, GEMM_SMEM>>>(ahi, alo,
                                               wthi + 3 * WSTRIDE, wtlo + 3 * WSTRIDE,
                                               out, out, out, 0);
}

// round 13
// speedup vs baseline: 1.1620x; 1.1620x over previous
#include <cuda_runtime.h>
#include <cuda_fp16.h>
#include <cuda_bf16.h>
#include <math.h>
#include <cstdint>

// Problem constants
#define BB 4
#define SS 4096
#define DD 1024
#define HH 16
#define DH 64
#define MM (BB * SS)          // 16384 rows
#define CC 64                 // chunk length
#define NC (SS / CC)          // 64 chunks per sequence
#define EPS 1e-6f

// ---------------------------------------------------------------------------
// Scratch (device globals; no allocation allowed)
// ---------------------------------------------------------------------------
__device__ __align__(256) float g_q[(size_t)MM * DD];
__device__ __align__(256) float g_k[(size_t)MM * DD];
__device__ __align__(256) float g_v[(size_t)MM * DD];
__device__ __align__(256) __half g_xhi[(size_t)MM * DD];
__device__ __align__(256) __half g_xlo[(size_t)MM * DD];
__device__ __align__(256) __half g_ahi[(size_t)MM * DD];
__device__ __align__(256) __half g_alo[(size_t)MM * DD];
// transposed weights [N,K] fp16 (single precision level — fp16 has enough
// mantissa), 4 weights (q,k,v,o) -- q,k,v contiguous for the fused GEMM
__device__ __align__(256) __half g_wt[4][(size_t)DD * DD];
// chunk states: [B*H][NC][DH][DH]
__device__ __align__(256) float g_cS[(size_t)BB * HH * NC * DH * DH];
__device__ __align__(256) float g_cz[(size_t)BB * HH * NC * DH];

// ---------------------------------------------------------------------------
// Warp-MMA + cp.async helpers (sm_80-era PTX; assembles for sm_103)
// ---------------------------------------------------------------------------
__device__ __forceinline__ uint32_t smem_u32(const void* p) {
    uint32_t a;
    asm("{ .reg .u64 t; cvta.to.shared.u64 t, %1; cvt.u32.u64 %0, t; }"
        : "=r"(a) : "l"(p));
    return a;
}
__device__ __forceinline__ void ldsm_x4(uint32_t* r, uint32_t addr) {
    asm volatile("ldmatrix.sync.aligned.m8n8.x4.shared.b16 {%0,%1,%2,%3}, [%4];"
                 : "=r"(r[0]), "=r"(r[1]), "=r"(r[2]), "=r"(r[3]) : "r"(addr));
}
__device__ __forceinline__ void mma_fp16(float* d, const uint32_t* a,
                                         uint32_t b0, uint32_t b1) {
    asm volatile(
        "mma.sync.aligned.m16n8k16.row.col.f32.f16.f16.f32 "
        "{%0,%1,%2,%3}, {%4,%5,%6,%7}, {%8,%9}, {%0,%1,%2,%3};"
        : "+f"(d[0]), "+f"(d[1]), "+f"(d[2]), "+f"(d[3])
        : "r"(a[0]), "r"(a[1]), "r"(a[2]), "r"(a[3]), "r"(b0), "r"(b1));
}
__device__ __forceinline__ void cpa16(uint32_t dst, const void* src) {
    asm volatile("cp.async.cg.shared.global [%0], [%1], 16;"
                 :: "r"(dst), "l"(src));
}
#define CP_COMMIT() asm volatile("cp.async.commit_group;" ::: "memory")
#define CP_WAIT1()  asm volatile("cp.async.wait_group 1;" ::: "memory")

// ---------------------------------------------------------------------------
// Pipelined mma.sync fp16 GEMM, A split hi/lo (2 accumulating passes):
// C[:,n] = (Ahi+Alo)[M,K] @ B[Ntot,K]^T, fp32 out.
// CTA 128x128, BK=32, 16 warps (4x4), warp tile 32x32.
// 2-stage cp.async double buffering (R10 shape: wait+bar, compute, bar,
// issue next). which=n0>>10 selects output; phimask bit -> elu+1 epilogue.
// ---------------------------------------------------------------------------
#define GBK 32
#define NKCH (DD / GBK)       // 32
#define ASTR 40               // padded smem row stride (halfs) - conflict-free
#define STG (128 * ASTR)      // elems per tile buffer
#define GEMM_SMEM (2 * 3 * STG * 2)   // 2 stages x 3 tiles x 10240 B = 61440

__global__ __launch_bounds__(512, 1) void gemm_mma(const __half* __restrict__ Ahi,
                                                   const __half* __restrict__ Alo,
                                                   const __half* __restrict__ Bw,
                                                   float* __restrict__ c0,
                                                   float* __restrict__ c1,
                                                   float* __restrict__ c2,
                                                   int phimask) {
    extern __shared__ __half smbuf[];
    uint32_t bsm = smem_u32(smbuf);

    int tid  = threadIdx.x;
    int wid  = tid >> 5;      // 0..15
    int lane = tid & 31;
    int wr   = wid >> 2;      // 0..3  (M, 32 rows each)
    int wc   = wid & 3;       // 0..3  (N, 32 cols each)
    int m0   = blockIdx.y * 128;
    int n0   = blockIdx.x * 128;

    // per-thread load coords: ONE 16B chunk per tile per stage (512*16B = tile)
    int rc = tid >> 2;
    int cc = (tid & 3) * 8;
    uint32_t off = (uint32_t)(rc * ASTR + cc) * 2;

    const __half* gAh = Ahi + (size_t)(m0 + rc) * DD + cc;
    const __half* gAl = Alo + (size_t)(m0 + rc) * DD + cc;
    const __half* gB  = Bw  + (size_t)(n0 + rc) * DD + cc;

    auto issue = [&](int ch, int s) {
        int k0 = ch * GBK;
        uint32_t base = bsm + (uint32_t)(s * 3) * (uint32_t)(STG * 2);
        cpa16(base + 0 * STG * 2 + off, gAh + k0);
        cpa16(base + 1 * STG * 2 + off, gAl + k0);
        cpa16(base + 2 * STG * 2 + off, gB  + k0);
    };

    float acc[2][4][4];
#pragma unroll
    for (int i = 0; i < 2; ++i)
#pragma unroll
        for (int j = 0; j < 4; ++j)
#pragma unroll
            for (int r = 0; r < 4; ++r) acc[i][j][r] = 0.f;

    // ldmatrix base coords
    uint32_t aRow = wr * 32 + (lane & 15);
    uint32_t aCol = (lane >> 4) * 8;
    uint32_t bRow = wc * 32 + (lane & 7);
    uint32_t bCol = (lane >> 3) * 8;

    issue(0, 0); CP_COMMIT();
    issue(1, 1); CP_COMMIT();

    int cur = 0;
    for (int ch = 0; ch < NKCH; ++ch) {
        CP_WAIT1();
        __syncthreads();

        uint32_t base = bsm + (uint32_t)(cur * 3) * (uint32_t)(STG * 2);
        uint32_t bAh = base, bAl = base + STG * 2, bB = base + 2 * STG * 2;

        // B fragments for the whole BK=32 chunk: fb[nt][k-slice 0..3]
        uint32_t fb[4][4];
#pragma unroll
        for (int nt = 0; nt < 4; ++nt) {
            uint32_t o = ((bRow + nt * 8) * ASTR + bCol) * 2;
            ldsm_x4(fb[nt], bB + o);
        }
#pragma unroll
        for (int ks = 0; ks < 2; ++ks) {
            uint32_t fah[2][4], fal[2][4];
#pragma unroll
            for (int mt = 0; mt < 2; ++mt) {
                uint32_t o = ((aRow + mt * 16) * ASTR + ks * 16 + aCol) * 2;
                ldsm_x4(fah[mt], bAh + o);
                ldsm_x4(fal[mt], bAl + o);
            }
#pragma unroll
            for (int mt = 0; mt < 2; ++mt)
#pragma unroll
                for (int nt = 0; nt < 4; ++nt) {
                    uint32_t b0 = fb[nt][ks * 2], b1 = fb[nt][ks * 2 + 1];
                    mma_fp16(acc[mt][nt], fah[mt], b0, b1);   // Ah*B
                    mma_fp16(acc[mt][nt], fal[mt], b0, b1);   // Al*B
                }
        }
        __syncthreads();
        if (ch + 2 < NKCH) issue(ch + 2, cur);
        CP_COMMIT();
        cur ^= 1;
    }

    // epilogue
    int which = n0 >> 10;
    float* C  = (which == 0) ? c0 : ((which == 1) ? c1 : c2);
    int mode  = (phimask >> which) & 1;
    int ncol  = n0 & 1023;
    int erow  = m0 + wr * 32 + (lane >> 2);
    int ecol  = ncol + wc * 32 + (lane & 3) * 2;
#pragma unroll
    for (int mt = 0; mt < 2; ++mt) {
#pragma unroll
        for (int nt = 0; nt < 4; ++nt) {
            float v0 = acc[mt][nt][0], v1 = acc[mt][nt][1];
            float v2 = acc[mt][nt][2], v3 = acc[mt][nt][3];
            if (mode) {
                v0 = (v0 > 0.f) ? (v0 + 1.f) : expf(v0);
                v1 = (v1 > 0.f) ? (v1 + 1.f) : expf(v1);
                v2 = (v2 > 0.f) ? (v2 + 1.f) : expf(v2);
                v3 = (v3 > 0.f) ? (v3 + 1.f) : expf(v3);
            }
            float* p0 = C + (size_t)(erow + mt * 16) * DD + ecol + nt * 8;
            float* p1 = C + (size_t)(erow + mt * 16 + 8) * DD + ecol + nt * 8;
            *(float2*)p0 = make_float2(v0, v1);
            *(float2*)p1 = make_float2(v2, v3);
        }
    }
}

// ---------------------------------------------------------------------------
// x -> fp16 hi/lo split (elementwise)
// ---------------------------------------------------------------------------
__global__ __launch_bounds__(256) void convert_x(const float* __restrict__ x,
                                                 __half* __restrict__ hi,
                                                 __half* __restrict__ lo) {
    size_t i4 = ((size_t)blockIdx.x * 256 + threadIdx.x) * 4;
    float4 v = *(const float4*)(x + i4);
    __half h0 = __float2half(v.x), h1 = __float2half(v.y);
    __half h2 = __float2half(v.z), h3 = __float2half(v.w);
    __half l0 = __float2half(v.x - __half2float(h0));
    __half l1 = __float2half(v.y - __half2float(h1));
    __half l2 = __float2half(v.z - __half2float(h2));
    __half l3 = __float2half(v.w - __half2float(h3));
    __half2 ph0; ph0.x = h0; ph0.y = h1;
    __half2 ph1; ph1.x = h2; ph1.y = h3;
    __half2 pl0; pl0.x = l0; pl0.y = l1;
    __half2 pl1; pl1.x = l2; pl1.y = l3;
    *(__half2*)(hi + i4)     = ph0;
    *(__half2*)(hi + i4 + 2) = ph1;
    *(__half2*)(lo + i4)     = pl0;
    *(__half2*)(lo + i4 + 2) = pl1;
}

// ---------------------------------------------------------------------------
// All 4 weights: W [K,N] fp32 -> Wt [N,K] fp16 (transpose + quantize)
// grid (32,32,4); z selects weight
// ---------------------------------------------------------------------------
__global__ __launch_bounds__(256) void wconv_all(const float* __restrict__ W0,
                                                 const float* __restrict__ W1,
                                                 const float* __restrict__ W2,
                                                 const float* __restrict__ W3,
                                                 __half* __restrict__ WtB) {
    __shared__ float ts[32][33];
    int z = blockIdx.z;
    const float* W = (z == 0) ? W0 : (z == 1) ? W1 : (z == 2) ? W2 : W3;
    __half* Wt = WtB + (size_t)z * DD * DD;
    int n0 = blockIdx.x * 32, k0 = blockIdx.y * 32;
    int tx = threadIdx.x, ty = threadIdx.y;
#pragma unroll
    for (int j = 0; j < 4; ++j)
        ts[ty + j * 8][tx] = W[(size_t)(k0 + ty + j * 8) * DD + n0 + tx];
    __syncthreads();
#pragma unroll
    for (int j = 0; j < 4; ++j) {
        float v = ts[tx][ty + j * 8];
        Wt[(size_t)(n0 + ty + j * 8) * DD + k0 + tx] = __float2half(v);
    }
}

// ---------------------------------------------------------------------------
// Per-chunk sums: cS[bid] = K_chunk^T @ V_chunk (64x64), cz[bid] = colsum(K)
// ---------------------------------------------------------------------------
__global__ __launch_bounds__(256) void chunk_sums(const float* __restrict__ k,
                                                  const float* __restrict__ v,
                                                  float* __restrict__ cS,
                                                  float* __restrict__ cz) {
    __shared__ float Ks[64 * 64];
    __shared__ float Vs[64 * 64];

    int bid = blockIdx.x;
    int bh  = bid >> 6;
    int c   = bid & 63;
    int b   = bh >> 4;
    int tid = threadIdx.x;

    size_t gbase = ((size_t)(b * SS + c * CC)) * DD + (size_t)(bh & 15) * DH;
    for (int t4 = tid; t4 < 1024; t4 += 256) {
        int row = t4 >> 4;
        int c4  = (t4 & 15) * 4;
        *(float4*)&Ks[row * 64 + c4] = *(const float4*)&k[gbase + (size_t)row * DD + c4];
        *(float4*)&Vs[row * 64 + c4] = *(const float4*)&v[gbase + (size_t)row * DD + c4];
    }
    __syncthreads();

    int d  = tid >> 2;
    int eb = (tid & 3) * 16;
    float acc[16];
#pragma unroll
    for (int ee = 0; ee < 16; ++ee) acc[ee] = 0.f;

    for (int t = 0; t < 64; ++t) {
        float kd = Ks[t * 64 + d];
        const float4* vr = (const float4*)&Vs[t * 64 + eb];
        float4 v0 = vr[0], v1 = vr[1], v2 = vr[2], v3 = vr[3];
        acc[0]  += kd * v0.x; acc[1]  += kd * v0.y; acc[2]  += kd * v0.z; acc[3]  += kd * v0.w;
        acc[4]  += kd * v1.x; acc[5]  += kd * v1.y; acc[6]  += kd * v1.z; acc[7]  += kd * v1.w;
        acc[8]  += kd * v2.x; acc[9]  += kd * v2.y; acc[10] += kd * v2.z; acc[11] += kd * v2.w;
        acc[12] += kd * v3.x; acc[13] += kd * v3.y; acc[14] += kd * v3.z; acc[15] += kd * v3.w;
    }
    float* out = cS + (size_t)bid * 4096 + d * 64 + eb;
#pragma unroll
    for (int e4 = 0; e4 < 4; ++e4)
        *(float4*)&out[e4 * 4] = make_float4(acc[e4 * 4], acc[e4 * 4 + 1],
                                             acc[e4 * 4 + 2], acc[e4 * 4 + 3]);

    if (tid < 64) {
        float zsum = 0.f;
        for (int t = 0; t < 64; ++t) zsum += Ks[t * 64 + tid];
        cz[(size_t)bid * 64 + tid] = zsum;
    }
}

// ---------------------------------------------------------------------------
// Exclusive prefix over chunks, seeded with state_cache.
// ---------------------------------------------------------------------------
__global__ __launch_bounds__(256) void prefix_kernel(const float* __restrict__ cache,
                                                     float* __restrict__ cS,
                                                     float* __restrict__ cz) {
    int bh  = blockIdx.x;
    int tid = threadIdx.x;

    float run[16];
    {
        int f0 = tid * 16;
#pragma unroll
        for (int u = 0; u < 16; ++u) {
            int f = f0 + u;
            int d = f >> 6, e = f & 63;
            run[u] = cache[((size_t)bh * 65 + d) * 64 + e];
        }
    }
    float runz = (tid < 64) ? cache[((size_t)bh * 65 + 64) * 64 + tid] : 0.f;

    for (int c = 0; c < NC; ++c) {
        size_t base = ((size_t)(bh * NC + c)) * 4096 + (size_t)tid * 16;
#pragma unroll
        for (int u = 0; u < 16; ++u) {
            float t = cS[base + u];
            cS[base + u] = run[u];
            run[u] += t;
        }
        if (tid < 64) {
            size_t zb = ((size_t)(bh * NC + c)) * 64 + tid;
            float t = cz[zb];
            cz[zb] = runz;
            runz += t;
        }
    }
}

// ---------------------------------------------------------------------------
// Intra-chunk causal attention + inter-chunk state application.
// Writes fp16 hi/lo activations for the Wo GEMM.
// ---------------------------------------------------------------------------
#define PSTR 68
#define SMEM_INTRA ((5 * 64 * PSTR + 64) * 4)

__global__ __launch_bounds__(256) void intra_kernel(const float* __restrict__ q,
                                                    const float* __restrict__ k,
                                                    const float* __restrict__ v,
                                                    const float* __restrict__ cS,
                                                    const float* __restrict__ cz,
                                                    __half* __restrict__ ahi,
                                                    __half* __restrict__ alo) {
    extern __shared__ float sm[];
    float* Qs = sm;
    float* Ks = sm + 64 * PSTR;
    float* Vs = sm + 2 * 64 * PSTR;
    float* Ss = sm + 3 * 64 * PSTR;
    float* As = sm + 4 * 64 * PSTR;
    float* zs = sm + 5 * 64 * PSTR;

    int bid = blockIdx.x;
    int bh  = bid >> 6;
    int c   = bid & 63;
    int b   = bh >> 4;
    int tid = threadIdx.x;

    size_t gbase = ((size_t)(b * SS + c * CC)) * DD + (size_t)(bh & 15) * DH;
    for (int t4 = tid; t4 < 1024; t4 += 256) {
        int row = t4 >> 4;
        int c4  = (t4 & 15) * 4;
        size_t go = gbase + (size_t)row * DD + c4;
        *(float4*)&Qs[row * PSTR + c4] = *(const float4*)&q[go];
        *(float4*)&Ks[row * PSTR + c4] = *(const float4*)&k[go];
        *(float4*)&Vs[row * PSTR + c4] = *(const float4*)&v[go];
        *(float4*)&Ss[row * PSTR + c4] = *(const float4*)&cS[(size_t)bid * 4096 + (size_t)t4 * 4];
    }
    if (tid < 64) zs[tid] = cz[(size_t)bid * 64 + tid];
    __syncthreads();

    int i  = tid >> 2;
    int q4 = tid & 3;
    int eb = q4 * 16;
    const float* qrow = &Qs[i * PSTR];

    // Phase A: masked A row strip + den (strided j = jj*4+q4)
    float ap[16];
#pragma unroll
    for (int jj = 0; jj < 16; ++jj) ap[jj] = 0.f;
    for (int d = 0; d < 64; ++d) {
        float qd = qrow[d];
#pragma unroll
        for (int jj = 0; jj < 16; ++jj)
            ap[jj] += qd * Ks[(jj * 4 + q4) * PSTR + d];
    }
    float den = 0.f;
#pragma unroll
    for (int jj = 0; jj < 16; ++jj) {
        int j = jj * 4 + q4;
        if (j > i) ap[jj] = 0.f;
        As[i * PSTR + j] = ap[jj];
        den += ap[jj];
    }
#pragma unroll
    for (int dd = 0; dd < 16; ++dd) {
        int d = dd * 4 + q4;
        den += qrow[d] * zs[d];
    }
    den += __shfl_xor_sync(0xffffffffu, den, 1);
    den += __shfl_xor_sync(0xffffffffu, den, 2);
    float inv = 1.f / (den + EPS);
    __syncthreads();

    // Phase B: num = Q @ S_start + A @ V   (contiguous e = eb..eb+15, float4)
    float num[16];
#pragma unroll
    for (int ee = 0; ee < 16; ++ee) num[ee] = 0.f;
    for (int d = 0; d < 64; ++d) {
        float qd = qrow[d];
        const float4* sr = (const float4*)&Ss[d * PSTR + eb];
        float4 s0 = sr[0], s1 = sr[1], s2 = sr[2], s3 = sr[3];
        num[0]  += qd * s0.x; num[1]  += qd * s0.y; num[2]  += qd * s0.z; num[3]  += qd * s0.w;
        num[4]  += qd * s1.x; num[5]  += qd * s1.y; num[6]  += qd * s1.z; num[7]  += qd * s1.w;
        num[8]  += qd * s2.x; num[9]  += qd * s2.y; num[10] += qd * s2.z; num[11] += qd * s2.w;
        num[12] += qd * s3.x; num[13] += qd * s3.y; num[14] += qd * s3.z; num[15] += qd * s3.w;
    }
    for (int j = 0; j < 64; ++j) {
        float aij = As[i * PSTR + j];
        const float4* vr = (const float4*)&Vs[j * PSTR + eb];
        float4 v0 = vr[0], v1 = vr[1], v2 = vr[2], v3 = vr[3];
        num[0]  += aij * v0.x; num[1]  += aij * v0.y; num[2]  += aij * v0.z; num[3]  += aij * v0.w;
        num[4]  += aij * v1.x; num[5]  += aij * v1.y; num[6]  += aij * v1.z; num[7]  += aij * v1.w;
        num[8]  += aij * v2.x; num[9]  += aij * v2.y; num[10] += aij * v2.z; num[11] += aij * v2.w;
        num[12] += aij * v3.x; num[13] += aij * v3.y; num[14] += aij * v3.z; num[15] += aij * v3.w;
    }

    size_t obase = gbase + (size_t)i * DD + eb;
#pragma unroll
    for (int ee = 0; ee < 16; ++ee) {
        float r = num[ee] * inv;
        __half h = __float2half(r);
        __half l = __float2half(r - __half2float(h));
        ahi[obase + ee] = h;
        alo[obase + ee] = l;
    }
}

// ---------------------------------------------------------------------------
// Launch
// ---------------------------------------------------------------------------
extern "C" void kernel_launch(void* const* d_in, const int* in_sizes, int n_in,
                              void* d_out, int out_size) {
    const float* x     = (const float*)d_in[0];
    const float* cache = (const float*)d_in[1];
    const float* Wq    = (const float*)d_in[2];
    const float* Wk    = (const float*)d_in[3];
    const float* Wv    = (const float*)d_in[4];
    const float* Wo    = (const float*)d_in[5];
    float* out = (float*)d_out;

    float *qp, *kp, *vp, *cSp, *czp;
    __half *xhi, *xlo, *ahi, *alo, *wt;
    cudaGetSymbolAddress((void**)&qp,  g_q);
    cudaGetSymbolAddress((void**)&kp,  g_k);
    cudaGetSymbolAddress((void**)&vp,  g_v);
    cudaGetSymbolAddress((void**)&cSp, g_cS);
    cudaGetSymbolAddress((void**)&czp, g_cz);
    cudaGetSymbolAddress((void**)&xhi, g_xhi);
    cudaGetSymbolAddress((void**)&xlo, g_xlo);
    cudaGetSymbolAddress((void**)&ahi, g_ahi);
    cudaGetSymbolAddress((void**)&alo, g_alo);
    cudaGetSymbolAddress((void**)&wt,  g_wt);

    cudaFuncSetAttribute(intra_kernel, cudaFuncAttributeMaxDynamicSharedMemorySize,
                         SMEM_INTRA);
    cudaFuncSetAttribute(gemm_mma, cudaFuncAttributeMaxDynamicSharedMemorySize,
                         GEMM_SMEM);

    const size_t WSTRIDE = (size_t)DD * DD;
    const size_t HALF = (size_t)MM * DD / 2;

    // Launch order keeps the fused QKV GEMM at launch #4 for ncu capture.
    wconv_all<<<dim3(32, 32, 4), dim3(32, 8)>>>(Wq, Wk, Wv, Wo, wt);
    convert_x<<<MM * DD / 2048, 256>>>(x, xhi, xlo);
    convert_x<<<MM * DD / 2048, 256>>>(x + HALF, xhi + HALF, xlo + HALF);

    // Fused QKV GEMM: B rows span concatenated [Wq^T | Wk^T | Wv^T] (3072 rows)
    gemm_mma<<<dim3(24, 128), 512, GEMM_SMEM>>>(xhi, xlo, wt,
                                                qp, kp, vp, 0b011);

    chunk_sums<<<BB * HH * NC, 256>>>(kp, vp, cSp, czp);
    prefix_kernel<<<BB * HH, 256>>>(cache, cSp, czp);
    intra_kernel<<<BB * HH * NC, 256, SMEM_INTRA>>>(qp, kp, vp, cSp, czp, ahi, alo);

    // Wo GEMM
    gemm_mma<<<dim3(8, 128), 512, GEMM_SMEM>>>(ahi, alo, wt + 3 * WSTRIDE,
                                               out, out, out, 0);
}

// round 14
// speedup vs baseline: 2.6568x; 2.2864x over previous
#include <cuda_runtime.h>
#include <cuda_fp16.h>
#include <math.h>
#include <cstdint>

// Problem constants
#define BB 4
#define SS 4096
#define DD 1024
#define HH 16
#define DH 64
#define MM (BB * SS)          // 16384 rows
#define CC 64                 // chunk length
#define NC (SS / CC)          // 64 chunks per sequence
#define EPS 1e-6f

// ---------------------------------------------------------------------------
// Scratch (device globals; no allocation allowed)
// ---------------------------------------------------------------------------
__device__ __align__(256) __half g_xhi[(size_t)MM * DD];
__device__ __align__(256) __half g_xlo[(size_t)MM * DD];
__device__ __align__(256) __half g_qh[(size_t)MM * DD];
__device__ __align__(256) __half g_ql[(size_t)MM * DD];
__device__ __align__(256) __half g_kh[(size_t)MM * DD];
__device__ __align__(256) __half g_kl[(size_t)MM * DD];
__device__ __align__(256) __half g_vh[(size_t)MM * DD];
__device__ __align__(256) __half g_vl[(size_t)MM * DD];
__device__ __align__(256) __half g_ahi[(size_t)MM * DD];
__device__ __align__(256) __half g_alo[(size_t)MM * DD];
__device__ __align__(256) __half g_wt[4][(size_t)DD * DD];
// chunk states: raw sums fp32, exclusive-prefixed fp16 hi/lo
__device__ __align__(256) float  g_cS[(size_t)BB * HH * NC * DH * DH];
__device__ __align__(256) __half g_Shi[(size_t)BB * HH * NC * DH * DH];
__device__ __align__(256) __half g_Slo[(size_t)BB * HH * NC * DH * DH];
__device__ __align__(256) float  g_cz[(size_t)BB * HH * NC * DH];

// ---------------------------------------------------------------------------
// Warp-MMA + cp.async helpers
// ---------------------------------------------------------------------------
__device__ __forceinline__ uint32_t smem_u32(const void* p) {
    uint32_t a;
    asm("{ .reg .u64 t; cvta.to.shared.u64 t, %1; cvt.u32.u64 %0, t; }"
        : "=r"(a) : "l"(p));
    return a;
}
__device__ __forceinline__ void ldsm_x4(uint32_t* r, uint32_t addr) {
    asm volatile("ldmatrix.sync.aligned.m8n8.x4.shared.b16 {%0,%1,%2,%3}, [%4];"
                 : "=r"(r[0]), "=r"(r[1]), "=r"(r[2]), "=r"(r[3]) : "r"(addr));
}
__device__ __forceinline__ void ldsm_x4_t(uint32_t* r, uint32_t addr) {
    asm volatile("ldmatrix.sync.aligned.m8n8.x4.trans.shared.b16 {%0,%1,%2,%3}, [%4];"
                 : "=r"(r[0]), "=r"(r[1]), "=r"(r[2]), "=r"(r[3]) : "r"(addr));
}
__device__ __forceinline__ void mma_fp16(float* d, const uint32_t* a,
                                         uint32_t b0, uint32_t b1) {
    asm volatile(
        "mma.sync.aligned.m16n8k16.row.col.f32.f16.f16.f32 "
        "{%0,%1,%2,%3}, {%4,%5,%6,%7}, {%8,%9}, {%0,%1,%2,%3};"
        : "+f"(d[0]), "+f"(d[1]), "+f"(d[2]), "+f"(d[3])
        : "r"(a[0]), "r"(a[1]), "r"(a[2]), "r"(a[3]), "r"(b0), "r"(b1));
}
__device__ __forceinline__ void cpa16(uint32_t dst, const void* src) {
    asm volatile("cp.async.cg.shared.global [%0], [%1], 16;"
                 :: "r"(dst), "l"(src));
}
#define CP_COMMIT() asm volatile("cp.async.commit_group;" ::: "memory")
#define CP_WAIT1()  asm volatile("cp.async.wait_group 1;" ::: "memory")
#define CP_WAIT0()  asm volatile("cp.async.wait_group 0;" ::: "memory")

__device__ __forceinline__ __half2 split_hl(float v, __half& l) {
    __half h = __float2half(v);
    l = __float2half(v - __half2float(h));
    return __half2(h, l);  // unused pair; see call sites
}

// ---------------------------------------------------------------------------
// Pipelined mma.sync fp16 GEMM, A split hi/lo (2 accumulating passes).
// outmode 1: write q/k/v as fp16 hi/lo with phi on q,k.  outmode 0: fp32 to cf.
// ---------------------------------------------------------------------------
#define GBK 32
#define NKCH (DD / GBK)
#define ASTR 40
#define STG (128 * ASTR)
#define GEMM_SMEM (2 * 3 * STG * 2)

__global__ __launch_bounds__(512, 1) void gemm_mma(const __half* __restrict__ Ahi,
                                                   const __half* __restrict__ Alo,
                                                   const __half* __restrict__ Bw,
                                                   __half* __restrict__ oqh, __half* __restrict__ oql,
                                                   __half* __restrict__ okh, __half* __restrict__ okl,
                                                   __half* __restrict__ ovh, __half* __restrict__ ovl,
                                                   float* __restrict__ cf, int outmode) {
    extern __shared__ __half smbuf[];
    uint32_t bsm = smem_u32(smbuf);

    int tid  = threadIdx.x;
    int wid  = tid >> 5;
    int lane = tid & 31;
    int wr   = wid >> 2;
    int wc   = wid & 3;
    int m0   = blockIdx.y * 128;
    int n0   = blockIdx.x * 128;

    int rc = tid >> 2;
    int cc = (tid & 3) * 8;
    uint32_t off = (uint32_t)(rc * ASTR + cc) * 2;

    const __half* gAh = Ahi + (size_t)(m0 + rc) * DD + cc;
    const __half* gAl = Alo + (size_t)(m0 + rc) * DD + cc;
    const __half* gB  = Bw  + (size_t)(n0 + rc) * DD + cc;

    auto issue = [&](int ch, int s) {
        int k0 = ch * GBK;
        uint32_t base = bsm + (uint32_t)(s * 3) * (uint32_t)(STG * 2);
        cpa16(base + 0 * STG * 2 + off, gAh + k0);
        cpa16(base + 1 * STG * 2 + off, gAl + k0);
        cpa16(base + 2 * STG * 2 + off, gB  + k0);
    };

    float acc[2][4][4];
#pragma unroll
    for (int i = 0; i < 2; ++i)
#pragma unroll
        for (int j = 0; j < 4; ++j)
#pragma unroll
            for (int r = 0; r < 4; ++r) acc[i][j][r] = 0.f;

    uint32_t aRow = wr * 32 + (lane & 15);
    uint32_t aCol = (lane >> 4) * 8;
    uint32_t bRow = wc * 32 + (lane & 7);
    uint32_t bCol = (lane >> 3) * 8;

    issue(0, 0); CP_COMMIT();
    issue(1, 1); CP_COMMIT();

    int cur = 0;
    for (int ch = 0; ch < NKCH; ++ch) {
        CP_WAIT1();
        __syncthreads();

        uint32_t base = bsm + (uint32_t)(cur * 3) * (uint32_t)(STG * 2);
        uint32_t bAh = base, bAl = base + STG * 2, bB = base + 2 * STG * 2;

        uint32_t fb[4][4];
#pragma unroll
        for (int nt = 0; nt < 4; ++nt)
            ldsm_x4(fb[nt], bB + ((bRow + nt * 8) * ASTR + bCol) * 2);
#pragma unroll
        for (int ks = 0; ks < 2; ++ks) {
            uint32_t fah[2][4], fal[2][4];
#pragma unroll
            for (int mt = 0; mt < 2; ++mt) {
                uint32_t o = ((aRow + mt * 16) * ASTR + ks * 16 + aCol) * 2;
                ldsm_x4(fah[mt], bAh + o);
                ldsm_x4(fal[mt], bAl + o);
            }
#pragma unroll
            for (int mt = 0; mt < 2; ++mt)
#pragma unroll
                for (int nt = 0; nt < 4; ++nt) {
                    uint32_t b0 = fb[nt][ks * 2], b1 = fb[nt][ks * 2 + 1];
                    mma_fp16(acc[mt][nt], fah[mt], b0, b1);
                    mma_fp16(acc[mt][nt], fal[mt], b0, b1);
                }
        }
        __syncthreads();
        if (ch + 2 < NKCH) issue(ch + 2, cur);
        CP_COMMIT();
        cur ^= 1;
    }

    int which = n0 >> 10;
    int ncol  = n0 & 1023;
    int erow  = m0 + wr * 32 + (lane >> 2);
    int ecol  = ncol + wc * 32 + (lane & 3) * 2;

    if (outmode) {
        __half* oh = (which == 0) ? oqh : ((which == 1) ? okh : ovh);
        __half* ol = (which == 0) ? oql : ((which == 1) ? okl : ovl);
        int phi = (which != 2);
#pragma unroll
        for (int mt = 0; mt < 2; ++mt) {
#pragma unroll
            for (int nt = 0; nt < 4; ++nt) {
                float v0 = acc[mt][nt][0], v1 = acc[mt][nt][1];
                float v2 = acc[mt][nt][2], v3 = acc[mt][nt][3];
                if (phi) {
                    v0 = (v0 > 0.f) ? (v0 + 1.f) : expf(v0);
                    v1 = (v1 > 0.f) ? (v1 + 1.f) : expf(v1);
                    v2 = (v2 > 0.f) ? (v2 + 1.f) : expf(v2);
                    v3 = (v3 > 0.f) ? (v3 + 1.f) : expf(v3);
                }
                __half h0 = __float2half(v0), h1 = __float2half(v1);
                __half h2 = __float2half(v2), h3 = __float2half(v3);
                __half l0 = __float2half(v0 - __half2float(h0));
                __half l1 = __float2half(v1 - __half2float(h1));
                __half l2 = __float2half(v2 - __half2float(h2));
                __half l3 = __float2half(v3 - __half2float(h3));
                size_t p0 = (size_t)(erow + mt * 16) * DD + ecol + nt * 8;
                size_t p1 = (size_t)(erow + mt * 16 + 8) * DD + ecol + nt * 8;
                *(__half2*)&oh[p0] = __half2(h0, h1);
                *(__half2*)&oh[p1] = __half2(h2, h3);
                *(__half2*)&ol[p0] = __half2(l0, l1);
                *(__half2*)&ol[p1] = __half2(l2, l3);
            }
        }
    } else {
#pragma unroll
        for (int mt = 0; mt < 2; ++mt) {
#pragma unroll
            for (int nt = 0; nt < 4; ++nt) {
                float* p0 = cf + (size_t)(erow + mt * 16) * DD + ecol + nt * 8;
                float* p1 = cf + (size_t)(erow + mt * 16 + 8) * DD + ecol + nt * 8;
                *(float2*)p0 = make_float2(acc[mt][nt][0], acc[mt][nt][1]);
                *(float2*)p1 = make_float2(acc[mt][nt][2], acc[mt][nt][3]);
            }
        }
    }
}

// ---------------------------------------------------------------------------
// x -> fp16 hi/lo split
// ---------------------------------------------------------------------------
__global__ __launch_bounds__(256) void convert_x(const float* __restrict__ x,
                                                 __half* __restrict__ hi,
                                                 __half* __restrict__ lo) {
    size_t i4 = ((size_t)blockIdx.x * 256 + threadIdx.x) * 4;
    float4 v = *(const float4*)(x + i4);
    __half h0 = __float2half(v.x), h1 = __float2half(v.y);
    __half h2 = __float2half(v.z), h3 = __float2half(v.w);
    __half l0 = __float2half(v.x - __half2float(h0));
    __half l1 = __float2half(v.y - __half2float(h1));
    __half l2 = __float2half(v.z - __half2float(h2));
    __half l3 = __float2half(v.w - __half2float(h3));
    *(__half2*)(hi + i4)     = __half2(h0, h1);
    *(__half2*)(hi + i4 + 2) = __half2(h2, h3);
    *(__half2*)(lo + i4)     = __half2(l0, l1);
    *(__half2*)(lo + i4 + 2) = __half2(l2, l3);
}

// ---------------------------------------------------------------------------
// All 4 weights: W [K,N] fp32 -> Wt [N,K] fp16
// ---------------------------------------------------------------------------
__global__ __launch_bounds__(256) void wconv_all(const float* __restrict__ W0,
                                                 const float* __restrict__ W1,
                                                 const float* __restrict__ W2,
                                                 const float* __restrict__ W3,
                                                 __half* __restrict__ WtB) {
    __shared__ float ts[32][33];
    int z = blockIdx.z;
    const float* W = (z == 0) ? W0 : (z == 1) ? W1 : (z == 2) ? W2 : W3;
    __half* Wt = WtB + (size_t)z * DD * DD;
    int n0 = blockIdx.x * 32, k0 = blockIdx.y * 32;
    int tx = threadIdx.x, ty = threadIdx.y;
#pragma unroll
    for (int j = 0; j < 4; ++j)
        ts[ty + j * 8][tx] = W[(size_t)(k0 + ty + j * 8) * DD + n0 + tx];
    __syncthreads();
#pragma unroll
    for (int j = 0; j < 4; ++j)
        Wt[(size_t)(n0 + ty + j * 8) * DD + k0 + tx] = __float2half(ts[tx][ty + j * 8]);
}

// ---------------------------------------------------------------------------
// chunk_mma: cS[bid] = K^T V (fp32, 3-pass hi/lo MMA), cz[bid] = colsum(K).
// grid 4096, 256 threads (8 warps: wr 0-1 over d32, wc 0-3 over e16).
// ---------------------------------------------------------------------------
#define TSTR 72
#define ITILE (64 * TSTR)

__global__ __launch_bounds__(256) void chunk_mma(const __half* __restrict__ kh,
                                                 const __half* __restrict__ kl,
                                                 const __half* __restrict__ vh,
                                                 const __half* __restrict__ vl,
                                                 float* __restrict__ cS,
                                                 float* __restrict__ cz) {
    __shared__ __half tk_h[ITILE], tk_l[ITILE], tv_h[ITILE], tv_l[ITILE];

    int bid = blockIdx.x, bh = bid >> 6, c = bid & 63, b = bh >> 4, h = bh & 15;
    int tid = threadIdx.x, wid = tid >> 5, lane = tid & 31;
    int wr = wid >> 2, wc = wid & 3;

    size_t mrow = (size_t)(b * SS + c * CC);
    const __half* src[4] = {kh, kl, vh, vl};
    uint32_t dstb[4] = {smem_u32(tk_h), smem_u32(tk_l), smem_u32(tv_h), smem_u32(tv_l)};
#pragma unroll
    for (int t = 0; t < 4; ++t)
#pragma unroll
        for (int rep = 0; rep < 2; ++rep) {
            int u = tid + rep * 256;
            int row = u >> 3, seg = u & 7;
            cpa16(dstb[t] + (uint32_t)(row * TSTR + seg * 8) * 2,
                  src[t] + (mrow + row) * DD + h * DH + seg * 8);
        }
    CP_COMMIT(); CP_WAIT0();
    __syncthreads();

    float acc[2][2][4];
#pragma unroll
    for (int i = 0; i < 2; ++i)
#pragma unroll
        for (int j = 0; j < 2; ++j)
#pragma unroll
            for (int r = 0; r < 4; ++r) acc[i][j][r] = 0.f;

    uint32_t kbh = smem_u32(tk_h), kbl = smem_u32(tk_l);
    uint32_t vbh = smem_u32(tv_h), vbl = smem_u32(tv_l);
    // trans-A row/col lane offsets (A = K^T [d][t] from K [t][d])
    uint32_t taR = (lane & 7) + ((lane >> 4) << 3);          // t within chunk
    uint32_t taC = ((lane >> 3) & 1) << 3;                   // d within 16
    // trans-B (B = V [t][e] -> col-major [t][e])
    uint32_t tbR = (lane & 7) + (((lane >> 3) & 1) << 3);    // t within chunk
    uint32_t tbC = (lane >> 4) * 8;                          // e within 16

#pragma unroll
    for (int kc = 0; kc < 4; ++kc) {
        uint32_t fbh_[4], fbl_[4];
        uint32_t ob = ((kc * 16 + tbR) * TSTR + wc * 16 + tbC) * 2;
        ldsm_x4_t(fbh_, vbh + ob);
        ldsm_x4_t(fbl_, vbl + ob);
        uint32_t fah_[2][4], fal_[2][4];
#pragma unroll
        for (int mt = 0; mt < 2; ++mt) {
            uint32_t oa = ((kc * 16 + taR) * TSTR + wr * 32 + mt * 16 + taC) * 2;
            ldsm_x4_t(fah_[mt], kbh + oa);
            ldsm_x4_t(fal_[mt], kbl + oa);
        }
#pragma unroll
        for (int mt = 0; mt < 2; ++mt)
#pragma unroll
            for (int nt = 0; nt < 2; ++nt) {
                uint32_t b0 = fbh_[nt * 2], b1 = fbh_[nt * 2 + 1];
                uint32_t c0 = fbl_[nt * 2], c1 = fbl_[nt * 2 + 1];
                mma_fp16(acc[mt][nt], fah_[mt], b0, b1);
                mma_fp16(acc[mt][nt], fah_[mt], c0, c1);
                mma_fp16(acc[mt][nt], fal_[mt], b0, b1);
            }
    }

    // store cS
    int er = wr * 32 + (lane >> 2);
    int ec = wc * 16 + 2 * (lane & 3);
    float* outp = cS + (size_t)bid * 4096;
#pragma unroll
    for (int mt = 0; mt < 2; ++mt)
#pragma unroll
        for (int nt = 0; nt < 2; ++nt) {
            int r = er + mt * 16, cc2 = ec + nt * 8;
            *(float2*)&outp[(r)     * 64 + cc2] = make_float2(acc[mt][nt][0], acc[mt][nt][1]);
            *(float2*)&outp[(r + 8) * 64 + cc2] = make_float2(acc[mt][nt][2], acc[mt][nt][3]);
        }

    // colsum(K)
    if (tid < 64) {
        float z = 0.f;
        for (int t = 0; t < 64; ++t)
            z += __half2float(tk_h[t * TSTR + tid]) + __half2float(tk_l[t * TSTR + tid]);
        cz[(size_t)bid * 64 + tid] = z;
    }
}

// ---------------------------------------------------------------------------
// prefix: exclusive prefix over chunks (seeded by cache); S out as fp16 hi/lo.
// grid (64, 16), 256 thr; blockIdx.y==0 threads<64 also prefix z in place.
// ---------------------------------------------------------------------------
__global__ __launch_bounds__(256) void prefix_kernel(const float* __restrict__ cache,
                                                     const float* __restrict__ cS,
                                                     __half* __restrict__ Shi,
                                                     __half* __restrict__ Slo,
                                                     float* __restrict__ cz) {
    int bh = blockIdx.x;
    int f  = blockIdx.y * 256 + threadIdx.x;
    int d = f >> 6, e = f & 63;
    float run = cache[((size_t)bh * 65 + d) * 64 + e];

    for (int c = 0; c < NC; ++c) {
        size_t a = ((size_t)(bh * NC + c)) * 4096 + f;
        float t = cS[a];
        __half hp = __float2half(run);
        Shi[a] = hp;
        Slo[a] = __float2half(run - __half2float(hp));
        run += t;
    }
    if (blockIdx.y == 0 && threadIdx.x < 64) {
        int dz = threadIdx.x;
        float rz = cache[((size_t)bh * 65 + 64) * 64 + dz];
        for (int c = 0; c < NC; ++c) {
            size_t a = ((size_t)(bh * NC + c)) * 64 + dz;
            float t = cz[a];
            cz[a] = rz;
            rz += t;
        }
    }
}

// ---------------------------------------------------------------------------
// intra_mma: out = (Q@S_start + mask(QK^T)@V) / (q.z + rowsumA + eps)
// MMA 3-pass hi/lo everywhere; writes ahi/alo fp16.
// ---------------------------------------------------------------------------
#define INTRA_SMEM (8 * ITILE * 2 + 3 * 64 * 4)

__global__ __launch_bounds__(256) void intra_mma(const __half* __restrict__ qh,
                                                 const __half* __restrict__ ql,
                                                 const __half* __restrict__ kh,
                                                 const __half* __restrict__ kl,
                                                 const __half* __restrict__ vh,
                                                 const __half* __restrict__ vl,
                                                 const __half* __restrict__ Shg,
                                                 const __half* __restrict__ Slg,
                                                 const float* __restrict__ cz,
                                                 __half* __restrict__ ahi,
                                                 __half* __restrict__ alo) {
    extern __shared__ __half ism[];
    __half* tq_h = ism;             __half* tq_l = ism + ITILE;
    __half* tk_h = ism + 2 * ITILE; __half* tk_l = ism + 3 * ITILE;
    __half* tv_h = ism + 4 * ITILE; __half* tv_l = ism + 5 * ITILE;
    __half* tS_h = ism + 6 * ITILE; __half* tS_l = ism + 7 * ITILE;
    float* s_z   = (float*)(ism + 8 * ITILE);
    float* s_den = s_z + 64;
    float* s_inv = s_den + 64;
    __half* tA_h = tk_h;   // reuse after QK^T
    __half* tA_l = tk_l;

    int bid = blockIdx.x, bh = bid >> 6, c = bid & 63, b = bh >> 4, h = bh & 15;
    int tid = threadIdx.x, wid = tid >> 5, lane = tid & 31;
    int wr = wid >> 2, wc = wid & 3;   // wr: 32 rows, wc: 16 cols

    size_t mrow = (size_t)(b * SS + c * CC);
    {
        const __half* src[6] = {qh, ql, kh, kl, vh, vl};
        __half* dst[6] = {tq_h, tq_l, tk_h, tk_l, tv_h, tv_l};
#pragma unroll
        for (int t = 0; t < 6; ++t) {
            uint32_t db = smem_u32(dst[t]);
#pragma unroll
            for (int rep = 0; rep < 2; ++rep) {
                int u = tid + rep * 256;
                int row = u >> 3, seg = u & 7;
                cpa16(db + (uint32_t)(row * TSTR + seg * 8) * 2,
                      src[t] + (mrow + row) * DD + h * DH + seg * 8);
            }
        }
        uint32_t dh = smem_u32(tS_h), dl = smem_u32(tS_l);
#pragma unroll
        for (int rep = 0; rep < 2; ++rep) {
            int u = tid + rep * 256;
            int row = u >> 3, seg = u & 7;
            cpa16(dh + (uint32_t)(row * TSTR + seg * 8) * 2,
                  Shg + (size_t)bid * 4096 + u * 8);
            cpa16(dl + (uint32_t)(row * TSTR + seg * 8) * 2,
                  Slg + (size_t)bid * 4096 + u * 8);
        }
    }
    if (tid < 64) s_z[tid] = cz[(size_t)bid * 64 + tid];
    CP_COMMIT(); CP_WAIT0();
    __syncthreads();

    // den init = q . z
    {
        int i = tid >> 2, l4 = tid & 3;
        float a = 0.f;
        for (int d = l4 * 16; d < l4 * 16 + 16; ++d)
            a += (__half2float(tq_h[i * TSTR + d]) + __half2float(tq_l[i * TSTR + d])) * s_z[d];
        a += __shfl_xor_sync(0xffffffffu, a, 1);
        a += __shfl_xor_sync(0xffffffffu, a, 2);
        if (l4 == 0) s_den[i] = a;
    }
    __syncthreads();

    uint32_t qbh = smem_u32(tq_h), qbl = smem_u32(tq_l);
    uint32_t kbh = smem_u32(tk_h), kbl = smem_u32(tk_l);
    uint32_t vbh = smem_u32(tv_h), vbl = smem_u32(tv_l);
    uint32_t sbh = smem_u32(tS_h), sbl = smem_u32(tS_l);
    uint32_t abh = smem_u32(tA_h), abl = smem_u32(tA_l);

    uint32_t aRow = wr * 32 + (lane & 15);   // normal A: rows i
    uint32_t aCol = (lane >> 4) * 8;
    uint32_t bRowN = wc * 16 + (lane & 7);   // normal B: rows j (per ntile +8)
    uint32_t bColN = (lane >> 3) * 8;        // spans 32 k
    uint32_t tbR = (lane & 7) + (((lane >> 3) & 1) << 3);  // trans-B row(k16)
    uint32_t tbC = (lane >> 4) * 8;                        // trans-B col(n16)

    // ---- QK^T (A=Q normal, B=K normal) ----
    float fA[2][2][4];
#pragma unroll
    for (int i = 0; i < 2; ++i)
#pragma unroll
        for (int j = 0; j < 2; ++j)
#pragma unroll
            for (int r = 0; r < 4; ++r) fA[i][j][r] = 0.f;

#pragma unroll
    for (int kc = 0; kc < 2; ++kc) {       // 32-wide k chunks
        uint32_t fbh_[2][4], fbl_[2][4];
#pragma unroll
        for (int nt = 0; nt < 2; ++nt) {
            uint32_t ob = ((bRowN + nt * 8) * TSTR + kc * 32 + bColN) * 2;
            ldsm_x4(fbh_[nt], kbh + ob);
            ldsm_x4(fbl_[nt], kbl + ob);
        }
#pragma unroll
        for (int ks = 0; ks < 2; ++ks) {
            uint32_t fah_[2][4], fal_[2][4];
#pragma unroll
            for (int mt = 0; mt < 2; ++mt) {
                uint32_t oa = ((aRow + mt * 16) * TSTR + kc * 32 + ks * 16 + aCol) * 2;
                ldsm_x4(fah_[mt], qbh + oa);
                ldsm_x4(fal_[mt], qbl + oa);
            }
#pragma unroll
            for (int mt = 0; mt < 2; ++mt)
#pragma unroll
                for (int nt = 0; nt < 2; ++nt) {
                    uint32_t b0 = fbh_[nt][ks * 2], b1 = fbh_[nt][ks * 2 + 1];
                    uint32_t c0 = fbl_[nt][ks * 2], c1 = fbl_[nt][ks * 2 + 1];
                    mma_fp16(fA[mt][nt], fah_[mt], b0, b1);
                    mma_fp16(fA[mt][nt], fah_[mt], c0, c1);
                    mma_fp16(fA[mt][nt], fal_[mt], b0, b1);
                }
        }
    }

    // mask + rowsum
    int r0 = wr * 32 + (lane >> 2);
    int c0 = wc * 16 + 2 * (lane & 3);
#pragma unroll
    for (int mt = 0; mt < 2; ++mt) {
        float rsA = 0.f, rsB = 0.f;
#pragma unroll
        for (int nt = 0; nt < 2; ++nt) {
            int i0 = r0 + mt * 16, i1 = i0 + 8;
            int j0 = c0 + nt * 8, j1 = j0 + 1;
            if (j0 > i0) fA[mt][nt][0] = 0.f;
            if (j1 > i0) fA[mt][nt][1] = 0.f;
            if (j0 > i1) fA[mt][nt][2] = 0.f;
            if (j1 > i1) fA[mt][nt][3] = 0.f;
            rsA += fA[mt][nt][0] + fA[mt][nt][1];
            rsB += fA[mt][nt][2] + fA[mt][nt][3];
        }
        rsA += __shfl_xor_sync(0xffffffffu, rsA, 1);
        rsA += __shfl_xor_sync(0xffffffffu, rsA, 2);
        rsB += __shfl_xor_sync(0xffffffffu, rsB, 1);
        rsB += __shfl_xor_sync(0xffffffffu, rsB, 2);
        if ((lane & 3) == 0) {
            atomicAdd(&s_den[r0 + mt * 16], rsA);
            atomicAdd(&s_den[r0 + mt * 16 + 8], rsB);
        }
    }
    __syncthreads();   // atomics done; k tiles dead

    // store masked A hi/lo into (former k) smem
#pragma unroll
    for (int mt = 0; mt < 2; ++mt)
#pragma unroll
        for (int nt = 0; nt < 2; ++nt) {
            int i0 = r0 + mt * 16, i1 = i0 + 8, j0 = c0 + nt * 8;
            float v0 = fA[mt][nt][0], v1 = fA[mt][nt][1];
            float v2 = fA[mt][nt][2], v3 = fA[mt][nt][3];
            __half h0 = __float2half(v0), h1 = __float2half(v1);
            __half h2 = __float2half(v2), h3 = __float2half(v3);
            *(__half2*)&tA_h[i0 * TSTR + j0] = __half2(h0, h1);
            *(__half2*)&tA_h[i1 * TSTR + j0] = __half2(h2, h3);
            *(__half2*)&tA_l[i0 * TSTR + j0] =
                __half2(__float2half(v0 - __half2float(h0)), __float2half(v1 - __half2float(h1)));
            *(__half2*)&tA_l[i1 * TSTR + j0] =
                __half2(__float2half(v2 - __half2float(h2)), __float2half(v3 - __half2float(h3)));
        }
    if (tid < 64) s_inv[tid] = 1.f / (s_den[tid] + EPS);
    __syncthreads();

    // ---- out = Q@S (B=S trans) + A@V (B=V trans) ----
    float fO[2][2][4];
#pragma unroll
    for (int i = 0; i < 2; ++i)
#pragma unroll
        for (int j = 0; j < 2; ++j)
#pragma unroll
            for (int r = 0; r < 4; ++r) fO[i][j][r] = 0.f;

#pragma unroll
    for (int kc = 0; kc < 4; ++kc) {   // 16-wide k chunks
        uint32_t ob = ((kc * 16 + tbR) * TSTR + wc * 16 + tbC) * 2;
        uint32_t gsh[4], gsl[4], gvh[4], gvl[4];
        ldsm_x4_t(gsh, sbh + ob);
        ldsm_x4_t(gsl, sbl + ob);
        ldsm_x4_t(gvh, vbh + ob);
        ldsm_x4_t(gvl, vbl + ob);
        uint32_t fqh[2][4], fql[2][4], fxh[2][4], fxl[2][4];
#pragma unroll
        for (int mt = 0; mt < 2; ++mt) {
            uint32_t oa = ((aRow + mt * 16) * TSTR + kc * 16 + aCol) * 2;
            ldsm_x4(fqh[mt], qbh + oa);
            ldsm_x4(fql[mt], qbl + oa);
            ldsm_x4(fxh[mt], abh + oa);
            ldsm_x4(fxl[mt], abl + oa);
        }
#pragma unroll
        for (int mt = 0; mt < 2; ++mt)
#pragma unroll
            for (int nt = 0; nt < 2; ++nt) {
                uint32_t b0 = gsh[nt * 2], b1 = gsh[nt * 2 + 1];
                uint32_t c0r = gsl[nt * 2], c1r = gsl[nt * 2 + 1];
                mma_fp16(fO[mt][nt], fqh[mt], b0, b1);
                mma_fp16(fO[mt][nt], fqh[mt], c0r, c1r);
                mma_fp16(fO[mt][nt], fql[mt], b0, b1);
                uint32_t d0 = gvh[nt * 2], d1 = gvh[nt * 2 + 1];
                uint32_t e0 = gvl[nt * 2], e1 = gvl[nt * 2 + 1];
                mma_fp16(fO[mt][nt], fxh[mt], d0, d1);
                mma_fp16(fO[mt][nt], fxh[mt], e0, e1);
                mma_fp16(fO[mt][nt], fxl[mt], d0, d1);
            }
    }

    // scale by 1/den, split, store
#pragma unroll
    for (int mt = 0; mt < 2; ++mt) {
        float inv0 = s_inv[r0 + mt * 16];
        float inv1 = s_inv[r0 + mt * 16 + 8];
#pragma unroll
        for (int nt = 0; nt < 2; ++nt) {
            float v0 = fO[mt][nt][0] * inv0, v1 = fO[mt][nt][1] * inv0;
            float v2 = fO[mt][nt][2] * inv1, v3 = fO[mt][nt][3] * inv1;
            size_t m0g = mrow + r0 + mt * 16;
            size_t col = (size_t)h * DH + c0 + nt * 8;
            __half h0 = __float2half(v0), h1 = __float2half(v1);
            __half h2 = __float2half(v2), h3 = __float2half(v3);
            *(__half2*)&ahi[m0g * DD + col]       = __half2(h0, h1);
            *(__half2*)&ahi[(m0g + 8) * DD + col] = __half2(h2, h3);
            *(__half2*)&alo[m0g * DD + col] =
                __half2(__float2half(v0 - __half2float(h0)), __float2half(v1 - __half2float(h1)));
            *(__half2*)&alo[(m0g + 8) * DD + col] =
                __half2(__float2half(v2 - __half2float(h2)), __float2half(v3 - __half2float(h3)));
        }
    }
}

// ---------------------------------------------------------------------------
// Launch
// ---------------------------------------------------------------------------
extern "C" void kernel_launch(void* const* d_in, const int* in_sizes, int n_in,
                              void* d_out, int out_size) {
    const float* x     = (const float*)d_in[0];
    const float* cache = (const float*)d_in[1];
    const float* Wq    = (const float*)d_in[2];
    const float* Wk    = (const float*)d_in[3];
    const float* Wv    = (const float*)d_in[4];
    const float* Wo    = (const float*)d_in[5];
    float* out = (float*)d_out;

    __half *xhi, *xlo, *qh, *ql, *kh, *kl, *vh, *vl, *ahi, *alo, *wt, *Shi, *Slo;
    float *cSp, *czp;
    cudaGetSymbolAddress((void**)&xhi, g_xhi);
    cudaGetSymbolAddress((void**)&xlo, g_xlo);
    cudaGetSymbolAddress((void**)&qh,  g_qh);
    cudaGetSymbolAddress((void**)&ql,  g_ql);
    cudaGetSymbolAddress((void**)&kh,  g_kh);
    cudaGetSymbolAddress((void**)&kl,  g_kl);
    cudaGetSymbolAddress((void**)&vh,  g_vh);
    cudaGetSymbolAddress((void**)&vl,  g_vl);
    cudaGetSymbolAddress((void**)&ahi, g_ahi);
    cudaGetSymbolAddress((void**)&alo, g_alo);
    cudaGetSymbolAddress((void**)&wt,  g_wt);
    cudaGetSymbolAddress((void**)&Shi, g_Shi);
    cudaGetSymbolAddress((void**)&Slo, g_Slo);
    cudaGetSymbolAddress((void**)&cSp, g_cS);
    cudaGetSymbolAddress((void**)&czp, g_cz);

    cudaFuncSetAttribute(gemm_mma, cudaFuncAttributeMaxDynamicSharedMemorySize, GEMM_SMEM);
    cudaFuncSetAttribute(intra_mma, cudaFuncAttributeMaxDynamicSharedMemorySize, INTRA_SMEM);

    const size_t WSTRIDE = (size_t)DD * DD;

    wconv_all<<<dim3(32, 32, 4), dim3(32, 8)>>>(Wq, Wk, Wv, Wo, wt);
    convert_x<<<MM * DD / 1024, 256>>>(x, xhi, xlo);

    gemm_mma<<<dim3(24, 128), 512, GEMM_SMEM>>>(xhi, xlo, wt,
                                                qh, ql, kh, kl, vh, vl, out, 1);

    chunk_mma<<<BB * HH * NC, 256>>>(kh, kl, vh, vl, cSp, czp);
    prefix_kernel<<<dim3(BB * HH, 16), 256>>>(cache, cSp, Shi, Slo, czp);
    intra_mma<<<BB * HH * NC, 256, INTRA_SMEM>>>(qh, ql, kh, kl, vh, vl,
                                                 Shi, Slo, czp, ahi, alo);

    gemm_mma<<<dim3(8, 128), 512, GEMM_SMEM>>>(ahi, alo, wt + 3 * WSTRIDE,
                                               qh, ql, kh, kl, vh, vl, out, 0);
}

// round 15
// speedup vs baseline: 4.3769x; 1.6475x over previous
#include <cuda_runtime.h>
#include <cuda_fp16.h>
#include <math.h>
#include <cstdint>

// Problem constants
#define BB 4
#define SS 4096
#define DD 1024
#define HH 16
#define DH 64
#define MM (BB * SS)          // 16384 rows
#define CC 64                 // chunk length
#define NC (SS / CC)          // 64 chunks per sequence
#define EPS 1e-6f

// ---------------------------------------------------------------------------
// Scratch (device globals; no allocation allowed)
// ---------------------------------------------------------------------------
__device__ __align__(256) __half g_xhi[(size_t)MM * DD];
__device__ __align__(256) __half g_qh[(size_t)MM * DD];
__device__ __align__(256) __half g_kh[(size_t)MM * DD];
__device__ __align__(256) __half g_vh[(size_t)MM * DD];
__device__ __align__(256) __half g_ahi[(size_t)MM * DD];
__device__ __align__(256) __half g_wt[4][(size_t)DD * DD];
// chunk states: raw sums fp32, exclusive-prefixed fp16 hi/lo
__device__ __align__(256) float  g_cS[(size_t)BB * HH * NC * DH * DH];
__device__ __align__(256) __half g_Shi[(size_t)BB * HH * NC * DH * DH];
__device__ __align__(256) __half g_Slo[(size_t)BB * HH * NC * DH * DH];
__device__ __align__(256) float  g_cz[(size_t)BB * HH * NC * DH];

// ---------------------------------------------------------------------------
// Warp-MMA + cp.async helpers
// ---------------------------------------------------------------------------
__device__ __forceinline__ uint32_t smem_u32(const void* p) {
    uint32_t a;
    asm("{ .reg .u64 t; cvta.to.shared.u64 t, %1; cvt.u32.u64 %0, t; }"
        : "=r"(a) : "l"(p));
    return a;
}
__device__ __forceinline__ void ldsm_x4(uint32_t* r, uint32_t addr) {
    asm volatile("ldmatrix.sync.aligned.m8n8.x4.shared.b16 {%0,%1,%2,%3}, [%4];"
                 : "=r"(r[0]), "=r"(r[1]), "=r"(r[2]), "=r"(r[3]) : "r"(addr));
}
__device__ __forceinline__ void ldsm_x4_t(uint32_t* r, uint32_t addr) {
    asm volatile("ldmatrix.sync.aligned.m8n8.x4.trans.shared.b16 {%0,%1,%2,%3}, [%4];"
                 : "=r"(r[0]), "=r"(r[1]), "=r"(r[2]), "=r"(r[3]) : "r"(addr));
}
__device__ __forceinline__ void mma_fp16(float* d, const uint32_t* a,
                                         uint32_t b0, uint32_t b1) {
    asm volatile(
        "mma.sync.aligned.m16n8k16.row.col.f32.f16.f16.f32 "
        "{%0,%1,%2,%3}, {%4,%5,%6,%7}, {%8,%9}, {%0,%1,%2,%3};"
        : "+f"(d[0]), "+f"(d[1]), "+f"(d[2]), "+f"(d[3])
        : "r"(a[0]), "r"(a[1]), "r"(a[2]), "r"(a[3]), "r"(b0), "r"(b1));
}
__device__ __forceinline__ void cpa16(uint32_t dst, const void* src) {
    asm volatile("cp.async.cg.shared.global [%0], [%1], 16;"
                 :: "r"(dst), "l"(src));
}
#define CP_COMMIT() asm volatile("cp.async.commit_group;" ::: "memory")
#define CP_WAIT1()  asm volatile("cp.async.wait_group 1;" ::: "memory")
#define CP_WAIT0()  asm volatile("cp.async.wait_group 0;" ::: "memory")

// ---------------------------------------------------------------------------
// Pipelined mma.sync fp16 GEMM, SINGLE pass (A fp16, B fp16, fp32 accum).
// outmode 1: write q/k/v fp16 with phi on q,k.  outmode 0: fp32 to cf.
// CTA 128x128, BK=32, 16 warps (4x4), warp tile 32x32, 2-stage cp.async.
// ---------------------------------------------------------------------------
#define GBK 32
#define NKCH (DD / GBK)
#define ASTR 40
#define STG (128 * ASTR)
#define GEMM_SMEM (2 * 2 * STG * 2)   // 2 stages x 2 tiles x 10240 B = 40960

__global__ __launch_bounds__(512, 1) void gemm_mma(const __half* __restrict__ Ah,
                                                   const __half* __restrict__ Bw,
                                                   __half* __restrict__ oq,
                                                   __half* __restrict__ ok,
                                                   __half* __restrict__ ov,
                                                   float* __restrict__ cf, int outmode) {
    extern __shared__ __half smbuf[];
    uint32_t bsm = smem_u32(smbuf);

    int tid  = threadIdx.x;
    int wid  = tid >> 5;
    int lane = tid & 31;
    int wr   = wid >> 2;
    int wc   = wid & 3;
    int m0   = blockIdx.y * 128;
    int n0   = blockIdx.x * 128;

    int rc = tid >> 2;
    int cc = (tid & 3) * 8;
    uint32_t off = (uint32_t)(rc * ASTR + cc) * 2;

    const __half* gA = Ah + (size_t)(m0 + rc) * DD + cc;
    const __half* gB = Bw + (size_t)(n0 + rc) * DD + cc;

    auto issue = [&](int ch, int s) {
        int k0 = ch * GBK;
        uint32_t base = bsm + (uint32_t)(s * 2) * (uint32_t)(STG * 2);
        cpa16(base + off, gA + k0);
        cpa16(base + STG * 2 + off, gB + k0);
    };

    float acc[2][4][4];
#pragma unroll
    for (int i = 0; i < 2; ++i)
#pragma unroll
        for (int j = 0; j < 4; ++j)
#pragma unroll
            for (int r = 0; r < 4; ++r) acc[i][j][r] = 0.f;

    uint32_t aRow = wr * 32 + (lane & 15);
    uint32_t aCol = (lane >> 4) * 8;
    uint32_t bRow = wc * 32 + (lane & 7);
    uint32_t bCol = (lane >> 3) * 8;

    issue(0, 0); CP_COMMIT();
    issue(1, 1); CP_COMMIT();

    int cur = 0;
    for (int ch = 0; ch < NKCH; ++ch) {
        CP_WAIT1();
        __syncthreads();

        uint32_t base = bsm + (uint32_t)(cur * 2) * (uint32_t)(STG * 2);
        uint32_t bA = base, bB = base + STG * 2;

        uint32_t fb[4][4];
#pragma unroll
        for (int nt = 0; nt < 4; ++nt)
            ldsm_x4(fb[nt], bB + ((bRow + nt * 8) * ASTR + bCol) * 2);
#pragma unroll
        for (int ks = 0; ks < 2; ++ks) {
            uint32_t fa[2][4];
#pragma unroll
            for (int mt = 0; mt < 2; ++mt)
                ldsm_x4(fa[mt], bA + ((aRow + mt * 16) * ASTR + ks * 16 + aCol) * 2);
#pragma unroll
            for (int mt = 0; mt < 2; ++mt)
#pragma unroll
                for (int nt = 0; nt < 4; ++nt)
                    mma_fp16(acc[mt][nt], fa[mt], fb[nt][ks * 2], fb[nt][ks * 2 + 1]);
        }
        __syncthreads();
        if (ch + 2 < NKCH) issue(ch + 2, cur);
        CP_COMMIT();
        cur ^= 1;
    }

    int which = n0 >> 10;
    int ncol  = n0 & 1023;
    int erow  = m0 + wr * 32 + (lane >> 2);
    int ecol  = ncol + wc * 32 + (lane & 3) * 2;

    if (outmode) {
        __half* oh = (which == 0) ? oq : ((which == 1) ? ok : ov);
        int phi = (which != 2);
#pragma unroll
        for (int mt = 0; mt < 2; ++mt) {
#pragma unroll
            for (int nt = 0; nt < 4; ++nt) {
                float v0 = acc[mt][nt][0], v1 = acc[mt][nt][1];
                float v2 = acc[mt][nt][2], v3 = acc[mt][nt][3];
                if (phi) {
                    v0 = (v0 > 0.f) ? (v0 + 1.f) : expf(v0);
                    v1 = (v1 > 0.f) ? (v1 + 1.f) : expf(v1);
                    v2 = (v2 > 0.f) ? (v2 + 1.f) : expf(v2);
                    v3 = (v3 > 0.f) ? (v3 + 1.f) : expf(v3);
                }
                size_t p0 = (size_t)(erow + mt * 16) * DD + ecol + nt * 8;
                size_t p1 = (size_t)(erow + mt * 16 + 8) * DD + ecol + nt * 8;
                *(__half2*)&oh[p0] = __half2(__float2half(v0), __float2half(v1));
                *(__half2*)&oh[p1] = __half2(__float2half(v2), __float2half(v3));
            }
        }
    } else {
#pragma unroll
        for (int mt = 0; mt < 2; ++mt) {
#pragma unroll
            for (int nt = 0; nt < 4; ++nt) {
                float* p0 = cf + (size_t)(erow + mt * 16) * DD + ecol + nt * 8;
                float* p1 = cf + (size_t)(erow + mt * 16 + 8) * DD + ecol + nt * 8;
                *(float2*)p0 = make_float2(acc[mt][nt][0], acc[mt][nt][1]);
                *(float2*)p1 = make_float2(acc[mt][nt][2], acc[mt][nt][3]);
            }
        }
    }
}

// ---------------------------------------------------------------------------
// x -> fp16 (single)
// ---------------------------------------------------------------------------
__global__ __launch_bounds__(256) void convert_x(const float* __restrict__ x,
                                                 __half* __restrict__ hi) {
    size_t i4 = ((size_t)blockIdx.x * 256 + threadIdx.x) * 4;
    float4 v = *(const float4*)(x + i4);
    *(__half2*)(hi + i4)     = __half2(__float2half(v.x), __float2half(v.y));
    *(__half2*)(hi + i4 + 2) = __half2(__float2half(v.z), __float2half(v.w));
}

// ---------------------------------------------------------------------------
// All 4 weights: W [K,N] fp32 -> Wt [N,K] fp16
// ---------------------------------------------------------------------------
__global__ __launch_bounds__(256) void wconv_all(const float* __restrict__ W0,
                                                 const float* __restrict__ W1,
                                                 const float* __restrict__ W2,
                                                 const float* __restrict__ W3,
                                                 __half* __restrict__ WtB) {
    __shared__ float ts[32][33];
    int z = blockIdx.z;
    const float* W = (z == 0) ? W0 : (z == 1) ? W1 : (z == 2) ? W2 : W3;
    __half* Wt = WtB + (size_t)z * DD * DD;
    int n0 = blockIdx.x * 32, k0 = blockIdx.y * 32;
    int tx = threadIdx.x, ty = threadIdx.y;
#pragma unroll
    for (int j = 0; j < 4; ++j)
        ts[ty + j * 8][tx] = W[(size_t)(k0 + ty + j * 8) * DD + n0 + tx];
    __syncthreads();
#pragma unroll
    for (int j = 0; j < 4; ++j)
        Wt[(size_t)(n0 + ty + j * 8) * DD + k0 + tx] = __float2half(ts[tx][ty + j * 8]);
}

// ---------------------------------------------------------------------------
// chunk_mma: cS[bid] = K^T V (fp16 inputs exact, 1-pass), cz[bid] = colsum(K).
// ---------------------------------------------------------------------------
#define TSTR 72
#define ITILE (64 * TSTR)

__global__ __launch_bounds__(256) void chunk_mma(const __half* __restrict__ kh,
                                                 const __half* __restrict__ vh,
                                                 float* __restrict__ cS,
                                                 float* __restrict__ cz) {
    __shared__ __half tk[ITILE], tv[ITILE];

    int bid = blockIdx.x, bh = bid >> 6, c = bid & 63, b = bh >> 4, h = bh & 15;
    int tid = threadIdx.x, wid = tid >> 5, lane = tid & 31;
    int wr = wid >> 2, wc = wid & 3;

    size_t mrow = (size_t)(b * SS + c * CC);
    uint32_t kb = smem_u32(tk), vb = smem_u32(tv);
#pragma unroll
    for (int rep = 0; rep < 2; ++rep) {
        int u = tid + rep * 256;
        int row = u >> 3, seg = u & 7;
        cpa16(kb + (uint32_t)(row * TSTR + seg * 8) * 2,
              kh + (mrow + row) * DD + h * DH + seg * 8);
        cpa16(vb + (uint32_t)(row * TSTR + seg * 8) * 2,
              vh + (mrow + row) * DD + h * DH + seg * 8);
    }
    CP_COMMIT(); CP_WAIT0();
    __syncthreads();

    float acc[2][2][4];
#pragma unroll
    for (int i = 0; i < 2; ++i)
#pragma unroll
        for (int j = 0; j < 2; ++j)
#pragma unroll
            for (int r = 0; r < 4; ++r) acc[i][j][r] = 0.f;

    uint32_t taR = (lane & 7) + ((lane >> 4) << 3);
    uint32_t taC = ((lane >> 3) & 1) << 3;
    uint32_t tbR = (lane & 7) + (((lane >> 3) & 1) << 3);
    uint32_t tbC = (lane >> 4) * 8;

#pragma unroll
    for (int kc = 0; kc < 4; ++kc) {
        uint32_t fb[4];
        ldsm_x4_t(fb, vb + ((kc * 16 + tbR) * TSTR + wc * 16 + tbC) * 2);
        uint32_t fa[2][4];
#pragma unroll
        for (int mt = 0; mt < 2; ++mt)
            ldsm_x4_t(fa[mt], kb + ((kc * 16 + taR) * TSTR + wr * 32 + mt * 16 + taC) * 2);
#pragma unroll
        for (int mt = 0; mt < 2; ++mt)
#pragma unroll
            for (int nt = 0; nt < 2; ++nt)
                mma_fp16(acc[mt][nt], fa[mt], fb[nt * 2], fb[nt * 2 + 1]);
    }

    int er = wr * 32 + (lane >> 2);
    int ec = wc * 16 + 2 * (lane & 3);
    float* outp = cS + (size_t)bid * 4096;
#pragma unroll
    for (int mt = 0; mt < 2; ++mt)
#pragma unroll
        for (int nt = 0; nt < 2; ++nt) {
            int r = er + mt * 16, cc2 = ec + nt * 8;
            *(float2*)&outp[(r)     * 64 + cc2] = make_float2(acc[mt][nt][0], acc[mt][nt][1]);
            *(float2*)&outp[(r + 8) * 64 + cc2] = make_float2(acc[mt][nt][2], acc[mt][nt][3]);
        }

    if (tid < 64) {
        float z = 0.f;
        for (int t = 0; t < 64; ++t) z += __half2float(tk[t * TSTR + tid]);
        cz[(size_t)bid * 64 + tid] = z;
    }
}

// ---------------------------------------------------------------------------
// prefix: exclusive prefix over chunks (seeded by cache); S out as fp16 hi/lo.
// ---------------------------------------------------------------------------
__global__ __launch_bounds__(256) void prefix_kernel(const float* __restrict__ cache,
                                                     const float* __restrict__ cS,
                                                     __half* __restrict__ Shi,
                                                     __half* __restrict__ Slo,
                                                     float* __restrict__ cz) {
    int bh = blockIdx.x;
    int f  = blockIdx.y * 256 + threadIdx.x;
    int d = f >> 6, e = f & 63;
    float run = cache[((size_t)bh * 65 + d) * 64 + e];

    for (int c = 0; c < NC; ++c) {
        size_t a = ((size_t)(bh * NC + c)) * 4096 + f;
        float t = cS[a];
        __half hp = __float2half(run);
        Shi[a] = hp;
        Slo[a] = __float2half(run - __half2float(hp));
        run += t;
    }
    if (blockIdx.y == 0 && threadIdx.x < 64) {
        int dz = threadIdx.x;
        float rz = cache[((size_t)bh * 65 + 64) * 64 + dz];
        for (int c = 0; c < NC; ++c) {
            size_t a = ((size_t)(bh * NC + c)) * 64 + dz;
            float t = cz[a];
            cz[a] = rz;
            rz += t;
        }
    }
}

// ---------------------------------------------------------------------------
// intra_mma: out = (Q@S_start + mask(QK^T)@V) / (q.z + rowsumA + eps)
// q/k/v fp16 exact (1-pass QK^T); S hi/lo 2-pass; A hi/lo 2-pass. fp16 out.
// ---------------------------------------------------------------------------
#define INTRA_SMEM (6 * ITILE * 2 + 3 * 64 * 4)

__global__ __launch_bounds__(256) void intra_mma(const __half* __restrict__ qh,
                                                 const __half* __restrict__ kh,
                                                 const __half* __restrict__ vh,
                                                 const __half* __restrict__ Shg,
                                                 const __half* __restrict__ Slg,
                                                 const float* __restrict__ cz,
                                                 __half* __restrict__ ahi) {
    extern __shared__ __half ism[];
    __half* tq   = ism;
    __half* tk   = ism + ITILE;       // reused as A_hi after QK^T
    __half* tv   = ism + 2 * ITILE;
    __half* tS_h = ism + 3 * ITILE;
    __half* tS_l = ism + 4 * ITILE;
    __half* tA_l = ism + 5 * ITILE;
    float* s_z   = (float*)(ism + 6 * ITILE);
    float* s_den = s_z + 64;
    float* s_inv = s_den + 64;
    __half* tA_h = tk;

    int bid = blockIdx.x, bh = bid >> 6, c = bid & 63, b = bh >> 4, h = bh & 15;
    int tid = threadIdx.x, wid = tid >> 5, lane = tid & 31;
    int wr = wid >> 2, wc = wid & 3;

    size_t mrow = (size_t)(b * SS + c * CC);
    {
        const __half* src[3] = {qh, kh, vh};
        __half* dst[3] = {tq, tk, tv};
#pragma unroll
        for (int t = 0; t < 3; ++t) {
            uint32_t db = smem_u32(dst[t]);
#pragma unroll
            for (int rep = 0; rep < 2; ++rep) {
                int u = tid + rep * 256;
                int row = u >> 3, seg = u & 7;
                cpa16(db + (uint32_t)(row * TSTR + seg * 8) * 2,
                      src[t] + (mrow + row) * DD + h * DH + seg * 8);
            }
        }
        uint32_t dh = smem_u32(tS_h), dl = smem_u32(tS_l);
#pragma unroll
        for (int rep = 0; rep < 2; ++rep) {
            int u = tid + rep * 256;
            int row = u >> 3, seg = u & 7;
            cpa16(dh + (uint32_t)(row * TSTR + seg * 8) * 2,
                  Shg + (size_t)bid * 4096 + u * 8);
            cpa16(dl + (uint32_t)(row * TSTR + seg * 8) * 2,
                  Slg + (size_t)bid * 4096 + u * 8);
        }
    }
    if (tid < 64) s_z[tid] = cz[(size_t)bid * 64 + tid];
    CP_COMMIT(); CP_WAIT0();
    __syncthreads();

    // den init = q . z
    {
        int i = tid >> 2, l4 = tid & 3;
        float a = 0.f;
        for (int d = l4 * 16; d < l4 * 16 + 16; ++d)
            a += __half2float(tq[i * TSTR + d]) * s_z[d];
        a += __shfl_xor_sync(0xffffffffu, a, 1);
        a += __shfl_xor_sync(0xffffffffu, a, 2);
        if (l4 == 0) s_den[i] = a;
    }
    __syncthreads();

    uint32_t qb = smem_u32(tq), kb = smem_u32(tk), vb = smem_u32(tv);
    uint32_t sbh = smem_u32(tS_h), sbl = smem_u32(tS_l);
    uint32_t abh = smem_u32(tA_h), abl = smem_u32(tA_l);

    uint32_t aRow = wr * 32 + (lane & 15);
    uint32_t aCol = (lane >> 4) * 8;
    uint32_t bRowN = wc * 16 + (lane & 7);
    uint32_t bColN = (lane >> 3) * 8;
    uint32_t tbR = (lane & 7) + (((lane >> 3) & 1) << 3);
    uint32_t tbC = (lane >> 4) * 8;

    // ---- QK^T 1-pass (exact fp16 inputs) ----
    float fA[2][2][4];
#pragma unroll
    for (int i = 0; i < 2; ++i)
#pragma unroll
        for (int j = 0; j < 2; ++j)
#pragma unroll
            for (int r = 0; r < 4; ++r) fA[i][j][r] = 0.f;

#pragma unroll
    for (int kc = 0; kc < 2; ++kc) {
        uint32_t fb[2][4];
#pragma unroll
        for (int nt = 0; nt < 2; ++nt)
            ldsm_x4(fb[nt], kb + ((bRowN + nt * 8) * TSTR + kc * 32 + bColN) * 2);
#pragma unroll
        for (int ks = 0; ks < 2; ++ks) {
            uint32_t fa[2][4];
#pragma unroll
            for (int mt = 0; mt < 2; ++mt)
                ldsm_x4(fa[mt], qb + ((aRow + mt * 16) * TSTR + kc * 32 + ks * 16 + aCol) * 2);
#pragma unroll
            for (int mt = 0; mt < 2; ++mt)
#pragma unroll
                for (int nt = 0; nt < 2; ++nt)
                    mma_fp16(fA[mt][nt], fa[mt], fb[nt][ks * 2], fb[nt][ks * 2 + 1]);
        }
    }

    // mask + rowsum
    int r0 = wr * 32 + (lane >> 2);
    int c0 = wc * 16 + 2 * (lane & 3);
#pragma unroll
    for (int mt = 0; mt < 2; ++mt) {
        float rsA = 0.f, rsB = 0.f;
#pragma unroll
        for (int nt = 0; nt < 2; ++nt) {
            int i0 = r0 + mt * 16, i1 = i0 + 8;
            int j0 = c0 + nt * 8, j1 = j0 + 1;
            if (j0 > i0) fA[mt][nt][0] = 0.f;
            if (j1 > i0) fA[mt][nt][1] = 0.f;
            if (j0 > i1) fA[mt][nt][2] = 0.f;
            if (j1 > i1) fA[mt][nt][3] = 0.f;
            rsA += fA[mt][nt][0] + fA[mt][nt][1];
            rsB += fA[mt][nt][2] + fA[mt][nt][3];
        }
        rsA += __shfl_xor_sync(0xffffffffu, rsA, 1);
        rsA += __shfl_xor_sync(0xffffffffu, rsA, 2);
        rsB += __shfl_xor_sync(0xffffffffu, rsB, 1);
        rsB += __shfl_xor_sync(0xffffffffu, rsB, 2);
        if ((lane & 3) == 0) {
            atomicAdd(&s_den[r0 + mt * 16], rsA);
            atomicAdd(&s_den[r0 + mt * 16 + 8], rsB);
        }
    }
    __syncthreads();   // atomics done; k tile fragments consumed

    // store masked A hi/lo (A_hi overwrites k tile)
#pragma unroll
    for (int mt = 0; mt < 2; ++mt)
#pragma unroll
        for (int nt = 0; nt < 2; ++nt) {
            int i0 = r0 + mt * 16, i1 = i0 + 8, j0 = c0 + nt * 8;
            float v0 = fA[mt][nt][0], v1 = fA[mt][nt][1];
            float v2 = fA[mt][nt][2], v3 = fA[mt][nt][3];
            __half h0 = __float2half(v0), h1 = __float2half(v1);
            __half h2 = __float2half(v2), h3 = __float2half(v3);
            *(__half2*)&tA_h[i0 * TSTR + j0] = __half2(h0, h1);
            *(__half2*)&tA_h[i1 * TSTR + j0] = __half2(h2, h3);
            *(__half2*)&tA_l[i0 * TSTR + j0] =
                __half2(__float2half(v0 - __half2float(h0)), __float2half(v1 - __half2float(h1)));
            *(__half2*)&tA_l[i1 * TSTR + j0] =
                __half2(__float2half(v2 - __half2float(h2)), __float2half(v3 - __half2float(h3)));
        }
    if (tid < 64) s_inv[tid] = 1.f / (s_den[tid] + EPS);
    __syncthreads();

    // ---- out = Q@S (2-pass S hi/lo) + A@V (2-pass A hi/lo) ----
    float fO[2][2][4];
#pragma unroll
    for (int i = 0; i < 2; ++i)
#pragma unroll
        for (int j = 0; j < 2; ++j)
#pragma unroll
            for (int r = 0; r < 4; ++r) fO[i][j][r] = 0.f;

#pragma unroll
    for (int kc = 0; kc < 4; ++kc) {
        uint32_t ob = ((kc * 16 + tbR) * TSTR + wc * 16 + tbC) * 2;
        uint32_t gsh[4], gsl[4], gv[4];
        ldsm_x4_t(gsh, sbh + ob);
        ldsm_x4_t(gsl, sbl + ob);
        ldsm_x4_t(gv,  vb  + ob);
        uint32_t fq[2][4], fxh[2][4], fxl[2][4];
#pragma unroll
        for (int mt = 0; mt < 2; ++mt) {
            uint32_t oa = ((aRow + mt * 16) * TSTR + kc * 16 + aCol) * 2;
            ldsm_x4(fq[mt],  qb  + oa);
            ldsm_x4(fxh[mt], abh + oa);
            ldsm_x4(fxl[mt], abl + oa);
        }
#pragma unroll
        for (int mt = 0; mt < 2; ++mt)
#pragma unroll
            for (int nt = 0; nt < 2; ++nt) {
                mma_fp16(fO[mt][nt], fq[mt],  gsh[nt * 2], gsh[nt * 2 + 1]);
                mma_fp16(fO[mt][nt], fq[mt],  gsl[nt * 2], gsl[nt * 2 + 1]);
                mma_fp16(fO[mt][nt], fxh[mt], gv[nt * 2],  gv[nt * 2 + 1]);
                mma_fp16(fO[mt][nt], fxl[mt], gv[nt * 2],  gv[nt * 2 + 1]);
            }
    }

    // scale by 1/den, store fp16
#pragma unroll
    for (int mt = 0; mt < 2; ++mt) {
        float inv0 = s_inv[r0 + mt * 16];
        float inv1 = s_inv[r0 + mt * 16 + 8];
#pragma unroll
        for (int nt = 0; nt < 2; ++nt) {
            float v0 = fO[mt][nt][0] * inv0, v1 = fO[mt][nt][1] * inv0;
            float v2 = fO[mt][nt][2] * inv1, v3 = fO[mt][nt][3] * inv1;
            size_t m0g = mrow + r0 + mt * 16;
            size_t col = (size_t)h * DH + c0 + nt * 8;
            *(__half2*)&ahi[m0g * DD + col] =
                __half2(__float2half(v0), __float2half(v1));
            *(__half2*)&ahi[(m0g + 8) * DD + col] =
                __half2(__float2half(v2), __float2half(v3));
        }
    }
}

// ---------------------------------------------------------------------------
// Launch
// ---------------------------------------------------------------------------
extern "C" void kernel_launch(void* const* d_in, const int* in_sizes, int n_in,
                              void* d_out, int out_size) {
    const float* x     = (const float*)d_in[0];
    const float* cache = (const float*)d_in[1];
    const float* Wq    = (const float*)d_in[2];
    const float* Wk    = (const float*)d_in[3];
    const float* Wv    = (const float*)d_in[4];
    const float* Wo    = (const float*)d_in[5];
    float* out = (float*)d_out;

    __half *xhi, *qh, *kh, *vh, *ahi, *wt, *Shi, *Slo;
    float *cSp, *czp;
    cudaGetSymbolAddress((void**)&xhi, g_xhi);
    cudaGetSymbolAddress((void**)&qh,  g_qh);
    cudaGetSymbolAddress((void**)&kh,  g_kh);
    cudaGetSymbolAddress((void**)&vh,  g_vh);
    cudaGetSymbolAddress((void**)&ahi, g_ahi);
    cudaGetSymbolAddress((void**)&wt,  g_wt);
    cudaGetSymbolAddress((void**)&Shi, g_Shi);
    cudaGetSymbolAddress((void**)&Slo, g_Slo);
    cudaGetSymbolAddress((void**)&cSp, g_cS);
    cudaGetSymbolAddress((void**)&czp, g_cz);

    cudaFuncSetAttribute(gemm_mma, cudaFuncAttributeMaxDynamicSharedMemorySize, GEMM_SMEM);
    cudaFuncSetAttribute(intra_mma, cudaFuncAttributeMaxDynamicSharedMemorySize, INTRA_SMEM);

    const size_t WSTRIDE = (size_t)DD * DD;

    wconv_all<<<dim3(32, 32, 4), dim3(32, 8)>>>(Wq, Wk, Wv, Wo, wt);
    convert_x<<<MM * DD / 1024, 256>>>(x, xhi);

    // Fused QKV GEMM (1-pass fp16)
    gemm_mma<<<dim3(24, 128), 512, GEMM_SMEM>>>(xhi, wt, qh, kh, vh, out, 1);

    chunk_mma<<<BB * HH * NC, 256>>>(kh, vh, cSp, czp);
    prefix_kernel<<<dim3(BB * HH, 16), 256>>>(cache, cSp, Shi, Slo, czp);
    intra_mma<<<BB * HH * NC, 256, INTRA_SMEM>>>(qh, kh, vh, Shi, Slo, czp, ahi);

    // Wo GEMM (1-pass fp16)
    gemm_mma<<<dim3(8, 128), 512, GEMM_SMEM>>>(ahi, wt + 3 * WSTRIDE,
                                               qh, kh, vh, out, 0);
}